// round 13
// baseline (speedup 1.0000x reference)
#include <cuda_runtime.h>
#include <cuda_bf16.h>
#include <cstdint>

#define GRP 16
#define BSZ 8192
#define CH  256

// ---------------- scratch (device globals; no allocation allowed) ----------
__device__ float g_G[GRP * CH * CH];            // G = V^T V (upper blocks)
__device__ float g_Tinv[GRP * 8 * 32 * 32];     // diag-block inverses of R
__device__ __nv_bfloat16 g_Vhi[GRP * CH * CH];  // W split
__device__ __nv_bfloat16 g_Vlo[GRP * CH * CH];
__device__ __nv_bfloat16 g_Yhi[GRP * CH * CH];  // Y split
__device__ __nv_bfloat16 g_Ylo[GRP * CH * CH];
// Q^T hi/lo as pre-swizzled SMEM images: [GRP][8 chunks][16384 bytes]
__device__ unsigned char g_Qhi_sw[GRP * 8 * 16384];
__device__ unsigned char g_Qlo_sw[GRP * 8 * 16384];

__device__ __forceinline__ uint32_t smem_u32(const void* p) {
    uint32_t a;
    asm("{ .reg .u64 t; cvta.to.shared.u64 t, %1; cvt.u32.u64 %0, t; }"
        : "=r"(a) : "l"(p));
    return a;
}

#define LDSM4(r, addr)                                                      \
    asm volatile("ldmatrix.sync.aligned.m8n8.x4.shared.b16 {%0,%1,%2,%3}, [%4];" \
                 : "=r"((r)[0]), "=r"((r)[1]), "=r"((r)[2]), "=r"((r)[3])   \
                 : "r"(addr))
#define LDSM4T(r, addr)                                                     \
    asm volatile("ldmatrix.sync.aligned.m8n8.x4.trans.shared.b16 {%0,%1,%2,%3}, [%4];" \
                 : "=r"((r)[0]), "=r"((r)[1]), "=r"((r)[2]), "=r"((r)[3])   \
                 : "r"(addr))
#define MMA(c, a, b0, b1)                                                   \
    asm volatile("mma.sync.aligned.m16n8k16.row.col.f32.bf16.bf16.f32 "     \
                 "{%0,%1,%2,%3}, {%4,%5,%6,%7}, {%8,%9}, {%0,%1,%2,%3};"    \
                 : "+f"((c)[0]), "+f"((c)[1]), "+f"((c)[2]), "+f"((c)[3])   \
                 : "r"((a)[0]), "r"((a)[1]), "r"((a)[2]), "r"((a)[3]),      \
                   "r"(b0), "r"(b1))
#define CP16(dst, src)                                                      \
    asm volatile("cp.async.cg.shared.global [%0], [%1], 16;"                \
                 :: "r"(dst), "l"(src) : "memory")

__device__ __forceinline__ void mbar_wait(uint32_t mbar, uint32_t parity) {
    asm volatile(
        "{\n\t.reg .pred P;\n"
        "LW_%=:\n\t"
        "mbarrier.try_wait.parity.acquire.cta.shared::cta.b64 P, [%0], %1, 0x989680;\n\t"
        "@P bra LD_%=;\n\t"
        "bra LW_%=;\n"
        "LD_%=:\n\t}"
        :: "r"(mbar), "r"(parity) : "memory");
}

__device__ __forceinline__ uint32_t pack_hi(float a, float b) {
    __nv_bfloat16 x = __float2bfloat16(a), y = __float2bfloat16(b);
    return ((uint32_t)__bfloat16_as_ushort(y) << 16) | __bfloat16_as_ushort(x);
}
__device__ __forceinline__ uint32_t pack_lo(float a, float b) {
    __nv_bfloat16 x = __float2bfloat16(a), y = __float2bfloat16(b);
    __nv_bfloat16 lx = __float2bfloat16(a - __bfloat162float(x));
    __nv_bfloat16 ly = __float2bfloat16(b - __bfloat162float(y));
    return ((uint32_t)__bfloat16_as_ushort(ly) << 16) | __bfloat16_as_ushort(lx);
}

// ---------------- vsplit: W -> bf16 hi/lo ----------------------------------
__global__ void vsplit(const float* __restrict__ W) {
    int idx = (blockIdx.x * 256 + threadIdx.x) * 4;
    float4 v = *(const float4*)(W + idx);
    uint2 h, l;
    h.x = pack_hi(v.x, v.y); h.y = pack_hi(v.z, v.w);
    l.x = pack_lo(v.x, v.y); l.y = pack_lo(v.z, v.w);
    *(uint2*)&g_Vhi[idx] = h;
    *(uint2*)&g_Vlo[idx] = l;
}

// ---------------- g_mma: G = V^T V (upper 128x128 tiles, 512 thr) ----------
#define GSTRIDE 32768u
__global__ void __launch_bounds__(512) g_mma() {
    extern __shared__ __align__(1024) char sm[];
    const uint32_t sb = smem_u32(sm);
    int t = threadIdx.x, warp = t >> 5, lane = t & 31;
    int wm = warp >> 2, wn = warp & 3;      // warp tile 32m x 32n
    int g = blockIdx.y;
    int bx = blockIdx.x;                 // 0:(0,0) 1:(0,128) 2:(128,128)
    int a0 = (bx == 2) ? 128 : 0;
    int b0 = (bx == 0) ? 0 : 128;

    const __nv_bfloat16* Vh = g_Vhi + (size_t)g * CH * CH;
    const __nv_bfloat16* Vl = g_Vlo + (size_t)g * CH * CH;

    int kk = t >> 4, g0 = t & 15;
    auto stage = [&](int chk) {
        uint32_t d = sb + (uint32_t)(chk & 1) * GSTRIDE;
        int krow = chk * 32 + kk;
        uint32_t off = (uint32_t)kk * 256 + (uint32_t)((g0 ^ (kk & 7)) << 4);
        CP16(d + off,          Vh + (size_t)krow * CH + a0 + g0 * 8);
        CP16(d + 8192  + off,  Vl + (size_t)krow * CH + a0 + g0 * 8);
        CP16(d + 16384 + off,  Vh + (size_t)krow * CH + b0 + g0 * 8);
        CP16(d + 24576 + off,  Vl + (size_t)krow * CH + b0 + g0 * 8);
        asm volatile("cp.async.commit_group;" ::: "memory");
    };

    float acc[2][4][4] = {};
    stage(0);
    for (int ch = 0; ch < 8; ++ch) {
        asm volatile("cp.async.wait_group 0;" ::: "memory");
        __syncthreads();
        if (ch < 7) stage(ch + 1);
        uint32_t buf = sb + (uint32_t)(ch & 1) * GSTRIDE;
        #pragma unroll
        for (int ks = 0; ks < 32; ks += 16) {
            uint32_t ah[2][4], al[2][4];
            #pragma unroll
            for (int i = 0; i < 2; ++i) {
                uint32_t mb = (uint32_t)(wm * 32 + i * 16);
                uint32_t krow = (uint32_t)(ks + (lane & 7) + ((lane >> 4) << 3));
                uint32_t gran = (mb >> 3) + ((lane >> 3) & 1);
                uint32_t addr = buf + krow * 256u + ((gran ^ (krow & 7)) << 4);
                LDSM4T(ah[i], addr);
                LDSM4T(al[i], addr + 8192);
            }
            #pragma unroll
            for (int p = 0; p < 2; ++p) {
                uint32_t bh[4], bl[4];
                uint32_t krow = (uint32_t)(ks + (lane & 15));
                uint32_t gran = (uint32_t)(wn * 4 + p * 2 + (lane >> 4));
                uint32_t addr = buf + 16384 + krow * 256u + ((gran ^ (krow & 7)) << 4);
                LDSM4T(bh, addr);
                LDSM4T(bl, addr + 8192);
                #pragma unroll
                for (int i = 0; i < 2; ++i) {
                    MMA(acc[i][2 * p],     ah[i], bh[0], bh[1]);
                    MMA(acc[i][2 * p],     ah[i], bl[0], bl[1]);
                    MMA(acc[i][2 * p],     al[i], bh[0], bh[1]);
                    MMA(acc[i][2 * p + 1], ah[i], bh[2], bh[3]);
                    MMA(acc[i][2 * p + 1], ah[i], bl[2], bl[3]);
                    MMA(acc[i][2 * p + 1], al[i], bh[2], bh[3]);
                }
            }
        }
    }
    float* Gg = g_G + (size_t)g * CH * CH;
    #pragma unroll
    for (int i = 0; i < 2; ++i) {
        int row = a0 + wm * 32 + i * 16 + (lane >> 2);
        #pragma unroll
        for (int j = 0; j < 4; ++j) {
            int col = b0 + wn * 32 + j * 8 + (lane & 3) * 2;
            *(float2*)&Gg[(size_t)row * CH + col]       = make_float2(acc[i][j][0], acc[i][j][1]);
            *(float2*)&Gg[(size_t)(row + 8) * CH + col] = make_float2(acc[i][j][2], acc[i][j][3]);
        }
    }
}

// ---------------- tinv: invert 32x32 diagonal blocks of R (SMEM-staged) ----
#define TINV_SMEM ((8448 + 8448 + 256) * 4)
__global__ void __launch_bounds__(256) tinv_kernel() {
    extern __shared__ __align__(16) float S[];
    float* Gd  = S;            // 8 blocks [32][33]
    float* Ts  = S + 8448;     // 8 blocks [32][33]
    float* bet = S + 16896;

    int g = blockIdx.x;
    int t = threadIdx.x;
    const float* Gg = g_G + (size_t)g * CH * CH;

    for (int e = t; e < 8192; e += 256) {
        int kb = e >> 10, i = (e >> 5) & 31, k = e & 31;
        Gd[kb * 1056 + i * 33 + k] = Gg[(size_t)(kb * 32 + i) * CH + kb * 32 + k];
    }
    bet[t] = 2.0f / Gg[(size_t)t * CH + t];
    __syncthreads();

    int kb = t >> 5, j = t & 31;
    int c0 = kb * 32;
    float* Tb = Ts + kb * 1056;
    const float* Gb = Gd + kb * 1056;
    for (int i = j + 1; i < 32; ++i) Tb[i * 33 + j] = 0.f;
    Tb[j * 33 + j] = bet[c0 + j];
    for (int i = j - 1; i >= 0; --i) {
        float s = 0.f;
        for (int k = i + 1; k <= j; ++k)
            s += Gb[i * 33 + k] * Tb[k * 33 + j];
        Tb[i * 33 + j] = -bet[c0 + i] * s;
    }
    __syncthreads();
    float* Tg = g_Tinv + ((size_t)g * 8 + kb) * 1024;
    for (int i = 0; i < 32; ++i)
        Tg[i * 32 + j] = Tb[i * 33 + j];
}

// ---------------- Y = V R^{-1}: warp-parallel, vectorized accum ------------
#define YGU   0
#define YTD   28672
#define YYS   36864
#define YPRE  45312
#define YSP   46464
#define Y_SMEM_FLOATS 55680
#define Y_SMEM_BYTES  (Y_SMEM_FLOATS * 4)
__global__ void __launch_bounds__(256) y_kernel(const float* __restrict__ W) {
    extern __shared__ __align__(128) float S[];
    const uint32_t sb = smem_u32(S);
    int g  = blockIdx.y;
    int r0 = blockIdx.x * 32;
    int t  = threadIdx.x;

    const float* Vg = W + (size_t)g * CH * CH;
    const float* Gg = g_G + (size_t)g * CH * CH;

    // bulk-load strict-upper G (stride 32), Tinv, and V->Ys via cp.async
    {
        int rr = t >> 3, c = t & 7;
        int p = 0;
        for (int kb = 1; kb < 8; ++kb)
            for (int jc = 0; jc < kb; ++jc, ++p)
                CP16(sb + (uint32_t)(YGU + p * 1024 + rr * 32 + c * 4) * 4,
                     Gg + (size_t)(jc * 32 + rr) * CH + kb * 32 + c * 4);
        const float* Tg = g_Tinv + (size_t)g * 8 * 1024;
        for (int kb = 0; kb < 8; ++kb)
            CP16(sb + (uint32_t)(YTD + kb * 1024 + rr * 32 + c * 4) * 4,
                 Tg + (size_t)kb * 1024 + rr * 32 + c * 4);
        for (int cc = c; cc < 64; cc += 8)
            CP16(sb + (uint32_t)(YYS + rr * 264 + cc * 4) * 4,
                 Vg + (size_t)(r0 + rr) * CH + cc * 4);
        asm volatile("cp.async.commit_group;" ::: "memory");
        asm volatile("cp.async.wait_group 0;" ::: "memory");
    }
    __syncthreads();

    int w = t >> 5, l = t & 31;
    int q = l & 7, r2 = l >> 3;        // accumulation: 8 rows per thread
    int r = t >> 3, q8 = t & 7;        // reduction/Td: 1 row, 4 cols per thread

    for (int kb = 0; kb < 8; ++kb) {
        int c0 = kb * 32;
        // --- warp-parallel partial accumulation over jc blocks (vectorized)
        float a[8][4] = {};
        int pbase = kb * (kb - 1) / 2;
        for (int jc = w; jc < kb; jc += 8) {
            const float* Gb = S + YGU + (pbase + jc) * 1024;
            int j0 = jc * 32;
            #pragma unroll
            for (int jt = 0; jt < 4; ++jt) {
                float4 gg[8];
                #pragma unroll
                for (int u = 0; u < 8; ++u)
                    gg[u] = *(const float4*)(Gb + (jt * 8 + u) * 32 + 4 * q);
                #pragma unroll
                for (int ri = 0; ri < 8; ++ri) {
                    const float* Yr = S + YYS + (r2 + 4 * ri) * 264 + j0 + jt * 8;
                    float4 y0 = *(const float4*)(Yr);
                    float4 y1 = *(const float4*)(Yr + 4);
                    float yv[8] = {y0.x, y0.y, y0.z, y0.w, y1.x, y1.y, y1.z, y1.w};
                    #pragma unroll
                    for (int u = 0; u < 8; ++u) {
                        a[ri][0] += yv[u] * gg[u].x;
                        a[ri][1] += yv[u] * gg[u].y;
                        a[ri][2] += yv[u] * gg[u].z;
                        a[ri][3] += yv[u] * gg[u].w;
                    }
                }
            }
        }
        #pragma unroll
        for (int ri = 0; ri < 8; ++ri) {
            float4 v = {a[ri][0], a[ri][1], a[ri][2], a[ri][3]};
            *(float4*)(S + YSP + w * 1152 + (r2 + 4 * ri) * 36 + 4 * q) = v;
        }
        __syncthreads();
        // --- reduce partials; pre = V - sum  (Ys cols c0 still hold V)
        float4 pr = *(const float4*)(S + YYS + r * 264 + c0 + 4 * q8);
        #pragma unroll
        for (int w2 = 0; w2 < 8; ++w2) {
            float4 s = *(const float4*)(S + YSP + w2 * 1152 + r * 36 + 4 * q8);
            pr.x -= s.x; pr.y -= s.y; pr.z -= s.z; pr.w -= s.w;
        }
        *(float4*)(S + YPRE + r * 36 + 4 * q8) = pr;
        __syncwarp();
        // --- Y block = pre @ Td  (row-local within warp)
        const float* Tdb = S + YTD + kb * 1024 + 4 * q8;
        float o0 = 0.f, o1 = 0.f, o2 = 0.f, o3 = 0.f;
        #pragma unroll
        for (int i = 0; i < 32; ++i) {
            float pv = S[YPRE + r * 36 + i];
            float4 tv = *(const float4*)(Tdb + i * 32);
            o0 += pv * tv.x;
            o1 += pv * tv.y;
            o2 += pv * tv.z;
            o3 += pv * tv.w;
        }
        float4 ov = {o0, o1, o2, o3};
        *(float4*)(S + YYS + r * 264 + c0 + 4 * q8) = ov;
        __syncthreads();
    }

    for (int e = t; e < 32 * (CH / 2); e += 256) {
        int rr = e >> 7, cc = (e & 127) * 2;
        float v0 = S[YYS + rr * 264 + cc], v1 = S[YYS + rr * 264 + cc + 1];
        size_t idx = ((size_t)g * CH + r0 + rr) * CH + cc;
        *(uint32_t*)&g_Yhi[idx] = pack_hi(v0, v1);
        *(uint32_t*)&g_Ylo[idx] = pack_lo(v0, v1);
    }
}

// ---------------- q_mma: Q = I - Y V^T, 512 thr, pre-swizzled output -------
#define QSTRIDE 32768u
__global__ void __launch_bounds__(512) q_mma() {
    extern __shared__ __align__(1024) char sm[];
    const uint32_t sb = smem_u32(sm);
    int t = threadIdx.x, warp = t >> 5, lane = t & 31;
    int wm = warp >> 2, wn = warp & 3;      // warp tile 32m x 32n
    int g = blockIdx.y;
    int a0 = (blockIdx.x >> 1) * 128, b0 = (blockIdx.x & 1) * 128;

    const __nv_bfloat16* Yh = g_Yhi + (size_t)g * CH * CH;
    const __nv_bfloat16* Yl = g_Ylo + (size_t)g * CH * CH;
    const __nv_bfloat16* Vh = g_Vhi + (size_t)g * CH * CH;
    const __nv_bfloat16* Vl = g_Vlo + (size_t)g * CH * CH;

    int row = t >> 2, gp = t & 3;
    auto stage = [&](int chk) {
        uint32_t d = sb + (uint32_t)(chk & 1) * QSTRIDE;
        int k0 = chk * 32;
        uint32_t off = (uint32_t)row * 64 + (uint32_t)((gp ^ ((row >> 1) & 3)) << 4);
        CP16(d + off,          Yh + (size_t)(a0 + row) * CH + k0 + gp * 8);
        CP16(d + 8192  + off,  Yl + (size_t)(a0 + row) * CH + k0 + gp * 8);
        CP16(d + 16384 + off,  Vh + (size_t)(b0 + row) * CH + k0 + gp * 8);
        CP16(d + 24576 + off,  Vl + (size_t)(b0 + row) * CH + k0 + gp * 8);
        asm volatile("cp.async.commit_group;" ::: "memory");
    };

    float acc[2][4][4] = {};
    stage(0);
    for (int ch = 0; ch < 8; ++ch) {
        asm volatile("cp.async.wait_group 0;" ::: "memory");
        __syncthreads();
        if (ch < 7) stage(ch + 1);
        uint32_t buf = sb + (uint32_t)(ch & 1) * QSTRIDE;
        #pragma unroll
        for (int ks = 0; ks < 32; ks += 16) {
            uint32_t ah[2][4], al[2][4];
            #pragma unroll
            for (int i = 0; i < 2; ++i) {
                uint32_t mrow = (uint32_t)(wm * 32 + i * 16 + (lane & 15));
                uint32_t gran = (uint32_t)((ks >> 3) + (lane >> 4));
                uint32_t addr = buf + mrow * 64u + ((gran ^ ((mrow >> 1) & 3)) << 4);
                LDSM4(ah[i], addr);
                LDSM4(al[i], addr + 8192);
            }
            #pragma unroll
            for (int p = 0; p < 2; ++p) {
                uint32_t bh[4], bl[4];
                uint32_t nrow = (uint32_t)(wn * 32 + p * 16 + (lane & 7) + ((lane >> 4) << 3));
                uint32_t gran = (uint32_t)((ks >> 3) + ((lane >> 3) & 1));
                uint32_t addr = buf + 16384 + nrow * 64u + ((gran ^ ((nrow >> 1) & 3)) << 4);
                LDSM4(bh, addr);
                LDSM4(bl, addr + 8192);
                #pragma unroll
                for (int i = 0; i < 2; ++i) {
                    MMA(acc[i][2 * p],     ah[i], bh[0], bh[1]);
                    MMA(acc[i][2 * p],     ah[i], bl[0], bl[1]);
                    MMA(acc[i][2 * p],     al[i], bh[0], bh[1]);
                    MMA(acc[i][2 * p + 1], ah[i], bh[2], bh[3]);
                    MMA(acc[i][2 * p + 1], ah[i], bl[2], bl[3]);
                    MMA(acc[i][2 * p + 1], al[i], bh[2], bh[3]);
                }
            }
        }
    }
    // epilogue: write swizzled global images
    unsigned char* QH = g_Qhi_sw + (size_t)g * 8 * 16384;
    unsigned char* QL = g_Qlo_sw + (size_t)g * 8 * 16384;
    #pragma unroll
    for (int i = 0; i < 2; ++i) {
        int rr = a0 + wm * 32 + i * 16 + (lane >> 2);
        #pragma unroll
        for (int j = 0; j < 4; ++j) {
            int cc = b0 + wn * 32 + j * 8 + (lane & 3) * 2;
            float v0 = (rr == cc     ? 1.f : 0.f) - acc[i][j][0];
            float v1 = (rr == cc + 1 ? 1.f : 0.f) - acc[i][j][1];
            float v2 = (rr + 8 == cc     ? 1.f : 0.f) - acc[i][j][2];
            float v3 = (rr + 8 == cc + 1 ? 1.f : 0.f) - acc[i][j][3];
            int gran = cc >> 3, sub = (cc & 7) * 2;
            #pragma unroll
            for (int rh = 0; rh < 2; ++rh) {
                int k = rr + rh * 8;
                int chunk = k >> 5, krw = k & 31;
                size_t off = (size_t)chunk * 16384 + krw * 512 +
                             ((gran ^ (krw & 7)) << 4) + sub;
                *(uint32_t*)(QH + off) = pack_hi(rh ? v2 : v0, rh ? v3 : v1);
                *(uint32_t*)(QL + off) = pack_lo(rh ? v2 : v0, rh ? v3 : v1);
            }
        }
    }
}

// ---------------- out = x @ Q: mma.sync + 3-deep bulk B + A-prefetch -------
#define BM 128
#define BN 256
#define BK 32
#define ABUF 20480u          // per A buffer: hi 10240 + lo 10240
#define BBASE 40960u
#define BBUF 32768u          // per B buffer: hi 16384 + lo 16384
#define SMEM_TOTAL (BBASE + 3u * BBUF)   // 139264

__global__ void __launch_bounds__(512, 1) main_mma(const float* __restrict__ X,
                                                   float* __restrict__ out) {
    extern __shared__ __align__(1024) char sm[];
    __shared__ __align__(8) uint64_t mbars[3];
    const uint32_t sbase = smem_u32(sm);
    const uint32_t mb_base = smem_u32(mbars);

    int t = threadIdx.x;
    int warp = t >> 5, lane = t & 31;
    int wm = warp >> 3, wn = warp & 7;      // warp tile 64m x 32n
    int g = blockIdx.y;
    int m0 = blockIdx.x * BM;

    const float* Xg = X + ((size_t)g * BSZ + m0) * CH;
    const unsigned char* QH = g_Qhi_sw + (size_t)g * 8 * 16384;
    const unsigned char* QL = g_Qlo_sw + (size_t)g * 8 * 16384;

    if (t == 0) {
        asm volatile("mbarrier.init.shared.b64 [%0], 1;" :: "r"(mb_base) : "memory");
        asm volatile("mbarrier.init.shared.b64 [%0], 1;" :: "r"(mb_base + 8) : "memory");
        asm volatile("mbarrier.init.shared.b64 [%0], 1;" :: "r"(mb_base + 16) : "memory");
    }
    __syncthreads();

    int ar = t >> 2, ac = (t & 3) * 8;

    float acc[4][4][4] = {};
    float4 xa[2][2];

    auto loadA = [&](int ch) {
        xa[ch & 1][0] = *(const float4*)(Xg + (size_t)ar * CH + ch * BK + ac);
        xa[ch & 1][1] = *(const float4*)(Xg + (size_t)ar * CH + ch * BK + ac + 4);
    };
    auto issueB = [&](int ch) {   // call with t == 0 only
        int b = ch % 3;
        uint32_t mbar = mb_base + (uint32_t)b * 8;
        uint32_t dH = sbase + BBASE + (uint32_t)b * BBUF;
        uint32_t dL = dH + 16384u;
        const unsigned char* sH = QH + (size_t)ch * 16384;
        const unsigned char* sL = QL + (size_t)ch * 16384;
        asm volatile("mbarrier.arrive.expect_tx.shared.b64 _, [%0], %1;"
                     :: "r"(mbar), "r"(32768u) : "memory");
        asm volatile("cp.async.bulk.shared::cluster.global.mbarrier::complete_tx::bytes "
                     "[%0], [%1], %2, [%3];"
                     :: "r"(dH), "l"(sH), "r"(16384u), "r"(mbar) : "memory");
        asm volatile("cp.async.bulk.shared::cluster.global.mbarrier::complete_tx::bytes "
                     "[%0], [%1], %2, [%3];"
                     :: "r"(dL), "l"(sL), "r"(16384u), "r"(mbar) : "memory");
    };
    auto storeA = [&](int ch) {
        char* p = sm + (ch & 1) * ABUF;
        float4* x0 = &xa[ch & 1][0];
        float f[8] = {x0[0].x, x0[0].y, x0[0].z, x0[0].w,
                      x0[1].x, x0[1].y, x0[1].z, x0[1].w};
        uint32_t h[4], l[4];
        #pragma unroll
        for (int i = 0; i < 4; ++i) {
            h[i] = pack_hi(f[2 * i], f[2 * i + 1]);
            l[i] = pack_lo(f[2 * i], f[2 * i + 1]);
        }
        uint32_t ao = ar * 80u + ac * 2u;
        *(uint4*)(p + ao)         = make_uint4(h[0], h[1], h[2], h[3]);
        *(uint4*)(p + 10240 + ao) = make_uint4(l[0], l[1], l[2], l[3]);
    };

    loadA(0); loadA(1);
    if (t == 0) { issueB(0); issueB(1); }

    for (int ch = 0; ch < CH / BK; ++ch) {
        mbar_wait(mb_base + (uint32_t)(ch % 3) * 8, (uint32_t)((ch / 3) & 1));
        storeA(ch);
        __syncthreads();   // all warps past compute(ch-1); A(ch) visible
        if (t == 0 && ch + 2 < CH / BK) issueB(ch + 2);
        if (ch + 2 < CH / BK) loadA(ch + 2);

        uint32_t abuf = sbase + (uint32_t)(ch & 1) * ABUF;
        uint32_t bbuf = sbase + BBASE + (uint32_t)(ch % 3) * BBUF;
        #pragma unroll
        for (int ks = 0; ks < BK; ks += 16) {
            uint32_t ah[4][4], al[4][4];
            #pragma unroll
            for (int i = 0; i < 4; ++i) {
                uint32_t mrow = (uint32_t)(wm * 64 + i * 16 + (lane & 15));
                uint32_t kcol = (uint32_t)(ks + (lane >> 4) * 8);
                uint32_t addr = abuf + mrow * 80u + kcol * 2u;
                LDSM4(ah[i], addr);
                LDSM4(al[i], addr + 10240u);
            }
            #pragma unroll
            for (int p = 0; p < 2; ++p) {
                uint32_t bh[4], bl[4];
                uint32_t krow = (uint32_t)(ks + (lane & 15));
                uint32_t gran = (uint32_t)(wn * 4 + p * 2 + (lane >> 4));
                uint32_t addr = bbuf + krow * 512u + ((gran ^ (krow & 7)) << 4);
                LDSM4T(bh, addr);
                LDSM4T(bl, addr + 16384u);
                #pragma unroll
                for (int i = 0; i < 4; ++i) {
                    MMA(acc[i][2 * p],     ah[i], bh[0], bh[1]);
                    MMA(acc[i][2 * p],     ah[i], bl[0], bl[1]);
                    MMA(acc[i][2 * p],     al[i], bh[0], bh[1]);
                    MMA(acc[i][2 * p + 1], ah[i], bh[2], bh[3]);
                    MMA(acc[i][2 * p + 1], ah[i], bl[2], bl[3]);
                    MMA(acc[i][2 * p + 1], al[i], bh[2], bh[3]);
                }
            }
        }
    }

    // epilogue
    #pragma unroll
    for (int i = 0; i < 4; ++i) {
        int row = m0 + wm * 64 + i * 16 + (lane >> 2);
        float* o0 = out + ((size_t)g * BSZ + row) * CH + wn * 32 + (lane & 3) * 2;
        #pragma unroll
        for (int j = 0; j < 4; ++j) {
            *(float2*)(o0 + j * 8)          = make_float2(acc[i][j][0], acc[i][j][1]);
            *(float2*)(o0 + 8 * CH + j * 8) = make_float2(acc[i][j][2], acc[i][j][3]);
        }
    }
}

// ---------------- entry ----------------------------------------------------
extern "C" void kernel_launch(void* const* d_in, const int* in_sizes, int n_in,
                              void* d_out, int out_size) {
    const float* x = (const float*)d_in[0];
    const float* w = (const float*)d_in[1];
    if (n_in >= 2 && in_sizes[0] < in_sizes[1]) {
        const float* tmp = x; x = w; w = tmp;
    }
    float* out = (float*)d_out;

    cudaFuncSetAttribute(main_mma, cudaFuncAttributeMaxDynamicSharedMemorySize,
                         SMEM_TOTAL);
    cudaFuncSetAttribute(g_mma, cudaFuncAttributeMaxDynamicSharedMemorySize, 65536);
    cudaFuncSetAttribute(q_mma, cudaFuncAttributeMaxDynamicSharedMemorySize, 65536);
    cudaFuncSetAttribute(y_kernel, cudaFuncAttributeMaxDynamicSharedMemorySize,
                         Y_SMEM_BYTES);
    cudaFuncSetAttribute(tinv_kernel, cudaFuncAttributeMaxDynamicSharedMemorySize,
                         TINV_SMEM);

    vsplit<<<GRP * CH * CH / 1024, 256>>>(w);

    dim3 ggrid(3, GRP);
    g_mma<<<ggrid, 512, 65536>>>();

    tinv_kernel<<<GRP, 256, TINV_SMEM>>>();

    dim3 ygrid(CH / 32, GRP);
    y_kernel<<<ygrid, 256, Y_SMEM_BYTES>>>(w);

    dim3 qgrid(4, GRP);
    q_mma<<<qgrid, 512, 65536>>>();

    dim3 mgrid(BSZ / BM, GRP);
    main_mma<<<mgrid, 512, SMEM_TOTAL>>>(x, out);
}

// round 14
// speedup vs baseline: 1.0552x; 1.0552x over previous
#include <cuda_runtime.h>
#include <cuda_bf16.h>
#include <cstdint>

#define GRP 16
#define BSZ 8192
#define CH  256

// ---------------- scratch (device globals; no allocation allowed) ----------
__device__ float g_G[GRP * CH * CH];            // G = V^T V (upper blocks)
__device__ float g_Tinv[GRP * 8 * 32 * 32];     // diag-block inverses of R
__device__ __nv_bfloat16 g_Vhi[GRP * CH * CH];  // W split
__device__ __nv_bfloat16 g_Vlo[GRP * CH * CH];
__device__ __nv_bfloat16 g_Yhi[GRP * CH * CH];  // Y split
__device__ __nv_bfloat16 g_Ylo[GRP * CH * CH];
// Q^T hi/lo as pre-swizzled SMEM images: [GRP][8 chunks][16384 bytes]
__device__ unsigned char g_Qhi_sw[GRP * 8 * 16384];
__device__ unsigned char g_Qlo_sw[GRP * 8 * 16384];

__device__ __forceinline__ uint32_t smem_u32(const void* p) {
    uint32_t a;
    asm("{ .reg .u64 t; cvta.to.shared.u64 t, %1; cvt.u32.u64 %0, t; }"
        : "=r"(a) : "l"(p));
    return a;
}

#define LDSM4(r, addr)                                                      \
    asm volatile("ldmatrix.sync.aligned.m8n8.x4.shared.b16 {%0,%1,%2,%3}, [%4];" \
                 : "=r"((r)[0]), "=r"((r)[1]), "=r"((r)[2]), "=r"((r)[3])   \
                 : "r"(addr))
#define LDSM4T(r, addr)                                                     \
    asm volatile("ldmatrix.sync.aligned.m8n8.x4.trans.shared.b16 {%0,%1,%2,%3}, [%4];" \
                 : "=r"((r)[0]), "=r"((r)[1]), "=r"((r)[2]), "=r"((r)[3])   \
                 : "r"(addr))
#define MMA(c, a, b0, b1)                                                   \
    asm volatile("mma.sync.aligned.m16n8k16.row.col.f32.bf16.bf16.f32 "     \
                 "{%0,%1,%2,%3}, {%4,%5,%6,%7}, {%8,%9}, {%0,%1,%2,%3};"    \
                 : "+f"((c)[0]), "+f"((c)[1]), "+f"((c)[2]), "+f"((c)[3])   \
                 : "r"((a)[0]), "r"((a)[1]), "r"((a)[2]), "r"((a)[3]),      \
                   "r"(b0), "r"(b1))
#define CP16(dst, src)                                                      \
    asm volatile("cp.async.cg.shared.global [%0], [%1], 16;"                \
                 :: "r"(dst), "l"(src) : "memory")

__device__ __forceinline__ void mbar_wait(uint32_t mbar, uint32_t parity) {
    asm volatile(
        "{\n\t.reg .pred P;\n"
        "LW_%=:\n\t"
        "mbarrier.try_wait.parity.acquire.cta.shared::cta.b64 P, [%0], %1, 0x989680;\n\t"
        "@P bra LD_%=;\n\t"
        "bra LW_%=;\n"
        "LD_%=:\n\t}"
        :: "r"(mbar), "r"(parity) : "memory");
}

__device__ __forceinline__ uint32_t pack_hi(float a, float b) {
    __nv_bfloat16 x = __float2bfloat16(a), y = __float2bfloat16(b);
    return ((uint32_t)__bfloat16_as_ushort(y) << 16) | __bfloat16_as_ushort(x);
}
__device__ __forceinline__ uint32_t pack_lo(float a, float b) {
    __nv_bfloat16 x = __float2bfloat16(a), y = __float2bfloat16(b);
    __nv_bfloat16 lx = __float2bfloat16(a - __bfloat162float(x));
    __nv_bfloat16 ly = __float2bfloat16(b - __bfloat162float(y));
    return ((uint32_t)__bfloat16_as_ushort(ly) << 16) | __bfloat16_as_ushort(lx);
}

// ---------------- vsplit: W -> bf16 hi/lo ----------------------------------
__global__ void vsplit(const float* __restrict__ W) {
    int idx = (blockIdx.x * 256 + threadIdx.x) * 4;
    float4 v = *(const float4*)(W + idx);
    uint2 h, l;
    h.x = pack_hi(v.x, v.y); h.y = pack_hi(v.z, v.w);
    l.x = pack_lo(v.x, v.y); l.y = pack_lo(v.z, v.w);
    *(uint2*)&g_Vhi[idx] = h;
    *(uint2*)&g_Vlo[idx] = l;
}

// ---------------- g_mma: G = V^T V (upper 128x128 tiles, HMMA) -------------
#define GSTRIDE 32768u
__global__ void __launch_bounds__(256) g_mma() {
    extern __shared__ __align__(1024) char sm[];
    const uint32_t sb = smem_u32(sm);
    int t = threadIdx.x, warp = t >> 5, lane = t & 31;
    int wm = warp >> 2, wn = warp & 3;
    int g = blockIdx.y;
    int bx = blockIdx.x;                 // 0:(0,0) 1:(0,128) 2:(128,128)
    int a0 = (bx == 2) ? 128 : 0;
    int b0 = (bx == 0) ? 0 : 128;

    const __nv_bfloat16* Vh = g_Vhi + (size_t)g * CH * CH;
    const __nv_bfloat16* Vl = g_Vlo + (size_t)g * CH * CH;

    int kk = t >> 3, g0 = t & 7;
    auto stage = [&](int chk) {
        uint32_t d = sb + (uint32_t)(chk & 1) * GSTRIDE;
        int krow = chk * 32 + kk;
        #pragma unroll
        for (int gi = 0; gi < 2; ++gi) {
            int gr = g0 + gi * 8;
            uint32_t off = (uint32_t)kk * 256 + (uint32_t)((gr ^ (kk & 7)) << 4);
            CP16(d + off,          Vh + (size_t)krow * CH + a0 + gr * 8);
            CP16(d + 8192  + off,  Vl + (size_t)krow * CH + a0 + gr * 8);
            CP16(d + 16384 + off,  Vh + (size_t)krow * CH + b0 + gr * 8);
            CP16(d + 24576 + off,  Vl + (size_t)krow * CH + b0 + gr * 8);
        }
        asm volatile("cp.async.commit_group;" ::: "memory");
    };

    float acc[4][4][4] = {};
    stage(0);
    for (int ch = 0; ch < 8; ++ch) {
        asm volatile("cp.async.wait_group 0;" ::: "memory");
        __syncthreads();
        if (ch < 7) stage(ch + 1);
        uint32_t buf = sb + (uint32_t)(ch & 1) * GSTRIDE;
        #pragma unroll
        for (int ks = 0; ks < 32; ks += 16) {
            uint32_t ah[4][4], al[4][4];
            #pragma unroll
            for (int i = 0; i < 4; ++i) {
                uint32_t mb = (uint32_t)(wm * 64 + i * 16);
                uint32_t krow = (uint32_t)(ks + (lane & 7) + ((lane >> 4) << 3));
                uint32_t gran = (mb >> 3) + ((lane >> 3) & 1);
                uint32_t addr = buf + krow * 256u + ((gran ^ (krow & 7)) << 4);
                LDSM4T(ah[i], addr);
                LDSM4T(al[i], addr + 8192);
            }
            #pragma unroll
            for (int p = 0; p < 2; ++p) {
                uint32_t bh[4], bl[4];
                uint32_t krow = (uint32_t)(ks + (lane & 15));
                uint32_t gran = (uint32_t)(wn * 4 + p * 2 + (lane >> 4));
                uint32_t addr = buf + 16384 + krow * 256u + ((gran ^ (krow & 7)) << 4);
                LDSM4T(bh, addr);
                LDSM4T(bl, addr + 8192);
                #pragma unroll
                for (int i = 0; i < 4; ++i) {
                    MMA(acc[i][2 * p],     ah[i], bh[0], bh[1]);
                    MMA(acc[i][2 * p],     ah[i], bl[0], bl[1]);
                    MMA(acc[i][2 * p],     al[i], bh[0], bh[1]);
                    MMA(acc[i][2 * p + 1], ah[i], bh[2], bh[3]);
                    MMA(acc[i][2 * p + 1], ah[i], bl[2], bl[3]);
                    MMA(acc[i][2 * p + 1], al[i], bh[2], bh[3]);
                }
            }
        }
    }
    float* Gg = g_G + (size_t)g * CH * CH;
    #pragma unroll
    for (int i = 0; i < 4; ++i) {
        int row = a0 + wm * 64 + i * 16 + (lane >> 2);
        #pragma unroll
        for (int j = 0; j < 4; ++j) {
            int col = b0 + wn * 32 + j * 8 + (lane & 3) * 2;
            *(float2*)&Gg[(size_t)row * CH + col]       = make_float2(acc[i][j][0], acc[i][j][1]);
            *(float2*)&Gg[(size_t)(row + 8) * CH + col] = make_float2(acc[i][j][2], acc[i][j][3]);
        }
    }
}

// ---------------- tinv: invert 32x32 diagonal blocks of R (SMEM-staged) ----
#define TINV_SMEM ((8448 + 8448 + 256) * 4)
__global__ void __launch_bounds__(256) tinv_kernel() {
    extern __shared__ __align__(16) float S[];
    float* Gd  = S;            // 8 blocks [32][33]
    float* Ts  = S + 8448;     // 8 blocks [32][33]
    float* bet = S + 16896;

    int g = blockIdx.x;
    int t = threadIdx.x;
    const float* Gg = g_G + (size_t)g * CH * CH;

    for (int e = t; e < 8192; e += 256) {
        int kb = e >> 10, i = (e >> 5) & 31, k = e & 31;
        Gd[kb * 1056 + i * 33 + k] = Gg[(size_t)(kb * 32 + i) * CH + kb * 32 + k];
    }
    bet[t] = 2.0f / Gg[(size_t)t * CH + t];
    __syncthreads();

    int kb = t >> 5, j = t & 31;
    int c0 = kb * 32;
    float* Tb = Ts + kb * 1056;
    const float* Gb = Gd + kb * 1056;
    for (int i = j + 1; i < 32; ++i) Tb[i * 33 + j] = 0.f;
    Tb[j * 33 + j] = bet[c0 + j];
    for (int i = j - 1; i >= 0; --i) {
        float s = 0.f;
        for (int k = i + 1; k <= j; ++k)
            s += Gb[i * 33 + k] * Tb[k * 33 + j];
        Tb[i * 33 + j] = -bet[c0 + i] * s;
    }
    __syncthreads();
    float* Tg = g_Tinv + ((size_t)g * 8 + kb) * 1024;
    for (int i = 0; i < 32; ++i)
        Tg[i * 32 + j] = Tb[i * 33 + j];
}

// ---------------- Y = V R^{-1}: warp-parallel jc accumulation --------------
#define YGU   0
#define YTD   28672
#define YYS   36864
#define YPRE  45312
#define YSP   46464
#define Y_SMEM_FLOATS 55680
#define Y_SMEM_BYTES  (Y_SMEM_FLOATS * 4)
__global__ void __launch_bounds__(256) y_kernel(const float* __restrict__ W) {
    extern __shared__ __align__(128) float S[];
    const uint32_t sb = smem_u32(S);
    int g  = blockIdx.y;
    int r0 = blockIdx.x * 32;
    int t  = threadIdx.x;

    const float* Vg = W + (size_t)g * CH * CH;
    const float* Gg = g_G + (size_t)g * CH * CH;

    // bulk-load strict-upper G (stride 32), Tinv, and V->Ys via cp.async
    {
        int rr = t >> 3, c = t & 7;
        int p = 0;
        for (int kb = 1; kb < 8; ++kb)
            for (int jc = 0; jc < kb; ++jc, ++p)
                CP16(sb + (uint32_t)(YGU + p * 1024 + rr * 32 + c * 4) * 4,
                     Gg + (size_t)(jc * 32 + rr) * CH + kb * 32 + c * 4);
        const float* Tg = g_Tinv + (size_t)g * 8 * 1024;
        for (int kb = 0; kb < 8; ++kb)
            CP16(sb + (uint32_t)(YTD + kb * 1024 + rr * 32 + c * 4) * 4,
                 Tg + (size_t)kb * 1024 + rr * 32 + c * 4);
        for (int cc = c; cc < 64; cc += 8)
            CP16(sb + (uint32_t)(YYS + rr * 264 + cc * 4) * 4,
                 Vg + (size_t)(r0 + rr) * CH + cc * 4);
        asm volatile("cp.async.commit_group;" ::: "memory");
        asm volatile("cp.async.wait_group 0;" ::: "memory");
    }
    __syncthreads();

    int w = t >> 5, l = t & 31;
    int q = l & 7, r2 = l >> 3;        // accumulation: 8 rows per thread
    int r = t >> 3, q8 = t & 7;        // reduction/Td: 1 row, 4 cols per thread

    for (int kb = 0; kb < 8; ++kb) {
        int c0 = kb * 32;
        // --- warp-parallel partial accumulation over jc blocks
        float a[8][4] = {};
        int pbase = kb * (kb - 1) / 2;
        for (int jc = w; jc < kb; jc += 8) {
            const float* Gb = S + YGU + (pbase + jc) * 1024 + 4 * q;
            int j0 = jc * 32;
            #pragma unroll
            for (int jj = 0; jj < 32; ++jj) {
                float4 gg = *(const float4*)(Gb + jj * 32);
                #pragma unroll
                for (int ri = 0; ri < 8; ++ri) {
                    float yv = S[YYS + (r2 + 4 * ri) * 264 + j0 + jj];
                    a[ri][0] += yv * gg.x;
                    a[ri][1] += yv * gg.y;
                    a[ri][2] += yv * gg.z;
                    a[ri][3] += yv * gg.w;
                }
            }
        }
        #pragma unroll
        for (int ri = 0; ri < 8; ++ri) {
            float4 v = {a[ri][0], a[ri][1], a[ri][2], a[ri][3]};
            *(float4*)(S + YSP + w * 1152 + (r2 + 4 * ri) * 36 + 4 * q) = v;
        }
        __syncthreads();
        // --- reduce partials; pre = V - sum  (Ys cols c0 still hold V)
        float4 pr = *(const float4*)(S + YYS + r * 264 + c0 + 4 * q8);
        #pragma unroll
        for (int w2 = 0; w2 < 8; ++w2) {
            float4 s = *(const float4*)(S + YSP + w2 * 1152 + r * 36 + 4 * q8);
            pr.x -= s.x; pr.y -= s.y; pr.z -= s.z; pr.w -= s.w;
        }
        *(float4*)(S + YPRE + r * 36 + 4 * q8) = pr;
        __syncwarp();
        // --- Y block = pre @ Td  (row-local within warp)
        const float* Tdb = S + YTD + kb * 1024 + 4 * q8;
        float o0 = 0.f, o1 = 0.f, o2 = 0.f, o3 = 0.f;
        #pragma unroll
        for (int i = 0; i < 32; ++i) {
            float pv = S[YPRE + r * 36 + i];
            float4 tv = *(const float4*)(Tdb + i * 32);
            o0 += pv * tv.x;
            o1 += pv * tv.y;
            o2 += pv * tv.z;
            o3 += pv * tv.w;
        }
        float4 ov = {o0, o1, o2, o3};
        *(float4*)(S + YYS + r * 264 + c0 + 4 * q8) = ov;
        __syncthreads();
    }

    for (int e = t; e < 32 * (CH / 2); e += 256) {
        int rr = e >> 7, cc = (e & 127) * 2;
        float v0 = S[YYS + rr * 264 + cc], v1 = S[YYS + rr * 264 + cc + 1];
        size_t idx = ((size_t)g * CH + r0 + rr) * CH + cc;
        *(uint32_t*)&g_Yhi[idx] = pack_hi(v0, v1);
        *(uint32_t*)&g_Ylo[idx] = pack_lo(v0, v1);
    }
}

// ---------------- q_mma: Q = I - Y V^T, emits pre-swizzled Q images --------
#define QSTRIDE 32768u
__global__ void __launch_bounds__(256) q_mma() {
    extern __shared__ __align__(1024) char sm[];
    const uint32_t sb = smem_u32(sm);
    int t = threadIdx.x, warp = t >> 5, lane = t & 31;
    int wm = warp >> 2, wn = warp & 3;
    int g = blockIdx.y;
    int a0 = (blockIdx.x >> 1) * 128, b0 = (blockIdx.x & 1) * 128;

    const __nv_bfloat16* Yh = g_Yhi + (size_t)g * CH * CH;
    const __nv_bfloat16* Yl = g_Ylo + (size_t)g * CH * CH;
    const __nv_bfloat16* Vh = g_Vhi + (size_t)g * CH * CH;
    const __nv_bfloat16* Vl = g_Vlo + (size_t)g * CH * CH;

    int row = t >> 1, gp = (t & 1) * 2;
    auto stage = [&](int chk) {
        uint32_t d = sb + (uint32_t)(chk & 1) * QSTRIDE;
        int k0 = chk * 32;
        #pragma unroll
        for (int gi = 0; gi < 2; ++gi) {
            int gr = gp + gi;
            uint32_t off = (uint32_t)row * 64 + (uint32_t)((gr ^ ((row >> 1) & 3)) << 4);
            CP16(d + off,          Yh + (size_t)(a0 + row) * CH + k0 + gr * 8);
            CP16(d + 8192  + off,  Yl + (size_t)(a0 + row) * CH + k0 + gr * 8);
            CP16(d + 16384 + off,  Vh + (size_t)(b0 + row) * CH + k0 + gr * 8);
            CP16(d + 24576 + off,  Vl + (size_t)(b0 + row) * CH + k0 + gr * 8);
        }
        asm volatile("cp.async.commit_group;" ::: "memory");
    };

    float acc[4][4][4] = {};
    stage(0);
    for (int ch = 0; ch < 8; ++ch) {
        asm volatile("cp.async.wait_group 0;" ::: "memory");
        __syncthreads();
        if (ch < 7) stage(ch + 1);
        uint32_t buf = sb + (uint32_t)(ch & 1) * QSTRIDE;
        #pragma unroll
        for (int ks = 0; ks < 32; ks += 16) {
            uint32_t ah[4][4], al[4][4];
            #pragma unroll
            for (int i = 0; i < 4; ++i) {
                uint32_t mrow = (uint32_t)(wm * 64 + i * 16 + (lane & 15));
                uint32_t gran = (uint32_t)((ks >> 3) + (lane >> 4));
                uint32_t addr = buf + mrow * 64u + ((gran ^ ((mrow >> 1) & 3)) << 4);
                LDSM4(ah[i], addr);
                LDSM4(al[i], addr + 8192);
            }
            #pragma unroll
            for (int p = 0; p < 2; ++p) {
                uint32_t bh[4], bl[4];
                uint32_t nrow = (uint32_t)(wn * 32 + p * 16 + (lane & 7) + ((lane >> 4) << 3));
                uint32_t gran = (uint32_t)((ks >> 3) + ((lane >> 3) & 1));
                uint32_t addr = buf + 16384 + nrow * 64u + ((gran ^ ((nrow >> 1) & 3)) << 4);
                LDSM4(bh, addr);
                LDSM4(bl, addr + 8192);
                #pragma unroll
                for (int i = 0; i < 4; ++i) {
                    MMA(acc[i][2 * p],     ah[i], bh[0], bh[1]);
                    MMA(acc[i][2 * p],     ah[i], bl[0], bl[1]);
                    MMA(acc[i][2 * p],     al[i], bh[0], bh[1]);
                    MMA(acc[i][2 * p + 1], ah[i], bh[2], bh[3]);
                    MMA(acc[i][2 * p + 1], ah[i], bl[2], bl[3]);
                    MMA(acc[i][2 * p + 1], al[i], bh[2], bh[3]);
                }
            }
        }
    }
    // epilogue: write swizzled global images
    unsigned char* QH = g_Qhi_sw + (size_t)g * 8 * 16384;
    unsigned char* QL = g_Qlo_sw + (size_t)g * 8 * 16384;
    #pragma unroll
    for (int i = 0; i < 4; ++i) {
        int rr = a0 + wm * 64 + i * 16 + (lane >> 2);
        #pragma unroll
        for (int j = 0; j < 4; ++j) {
            int cc = b0 + wn * 32 + j * 8 + (lane & 3) * 2;
            float v0 = (rr == cc     ? 1.f : 0.f) - acc[i][j][0];
            float v1 = (rr == cc + 1 ? 1.f : 0.f) - acc[i][j][1];
            float v2 = (rr + 8 == cc     ? 1.f : 0.f) - acc[i][j][2];
            float v3 = (rr + 8 == cc + 1 ? 1.f : 0.f) - acc[i][j][3];
            int gran = cc >> 3, sub = (cc & 7) * 2;
            #pragma unroll
            for (int rh = 0; rh < 2; ++rh) {
                int k = rr + rh * 8;
                int chunk = k >> 5, krw = k & 31;
                size_t off = (size_t)chunk * 16384 + krw * 512 +
                             ((gran ^ (krw & 7)) << 4) + sub;
                *(uint32_t*)(QH + off) = pack_hi(rh ? v2 : v0, rh ? v3 : v1);
                *(uint32_t*)(QL + off) = pack_lo(rh ? v2 : v0, rh ? v3 : v1);
            }
        }
    }
}

// ---------------- out = x @ Q: BM=64, 2 CTAs/SM, bulk-B double buffer ------
#define BM 64
#define BN 256
#define BK 32
#define ABUF 10240u          // per A buffer: hi 5120 + lo 5120
#define BBASE 20480u
#define BBUF 32768u          // per B buffer: hi 16384 + lo 16384
#define SMEM_TOTAL (BBASE + 2u * BBUF)   // 86016

__global__ void __launch_bounds__(256, 2) main_mma(const float* __restrict__ X,
                                                   float* __restrict__ out) {
    extern __shared__ __align__(1024) char sm[];
    __shared__ __align__(8) uint64_t mbars[2];
    const uint32_t sbase = smem_u32(sm);
    const uint32_t mb_base = smem_u32(mbars);

    int t = threadIdx.x;
    int warp = t >> 5, lane = t & 31;
    int wm = warp >> 2, wn = warp & 3;      // warp tile 32m x 64n
    int g = blockIdx.y;
    int m0 = blockIdx.x * BM;

    const float* Xg = X + ((size_t)g * BSZ + m0) * CH;
    const unsigned char* QH = g_Qhi_sw + (size_t)g * 8 * 16384;
    const unsigned char* QL = g_Qlo_sw + (size_t)g * 8 * 16384;

    if (t == 0) {
        asm volatile("mbarrier.init.shared.b64 [%0], 1;" :: "r"(mb_base) : "memory");
        asm volatile("mbarrier.init.shared.b64 [%0], 1;" :: "r"(mb_base + 8) : "memory");
    }
    __syncthreads();

    int ar = t >> 2, ac = (t & 3) * 8;      // 64 rows x 32 cols, 8 cols/thread

    float acc[2][8][4] = {};
    float4 xa[2];

    auto loadA = [&](int ch) {
        xa[0] = *(const float4*)(Xg + (size_t)ar * CH + ch * BK + ac);
        xa[1] = *(const float4*)(Xg + (size_t)ar * CH + ch * BK + ac + 4);
    };
    auto issueB = [&](int ch) {   // call with t == 0 only
        int b = ch & 1;
        uint32_t mbar = mb_base + (uint32_t)b * 8;
        uint32_t dH = sbase + BBASE + (uint32_t)b * BBUF;
        uint32_t dL = dH + 16384u;
        const unsigned char* sH = QH + (size_t)ch * 16384;
        const unsigned char* sL = QL + (size_t)ch * 16384;
        asm volatile("mbarrier.arrive.expect_tx.shared.b64 _, [%0], %1;"
                     :: "r"(mbar), "r"(32768u) : "memory");
        asm volatile("cp.async.bulk.shared::cluster.global.mbarrier::complete_tx::bytes "
                     "[%0], [%1], %2, [%3];"
                     :: "r"(dH), "l"(sH), "r"(16384u), "r"(mbar) : "memory");
        asm volatile("cp.async.bulk.shared::cluster.global.mbarrier::complete_tx::bytes "
                     "[%0], [%1], %2, [%3];"
                     :: "r"(dL), "l"(sL), "r"(16384u), "r"(mbar) : "memory");
    };
    auto storeA = [&](int ch) {
        char* p = sm + (ch & 1) * ABUF;
        float f[8] = {xa[0].x, xa[0].y, xa[0].z, xa[0].w,
                      xa[1].x, xa[1].y, xa[1].z, xa[1].w};
        uint32_t h[4], l[4];
        #pragma unroll
        for (int i = 0; i < 4; ++i) {
            h[i] = pack_hi(f[2 * i], f[2 * i + 1]);
            l[i] = pack_lo(f[2 * i], f[2 * i + 1]);
        }
        uint32_t ao = ar * 80u + ac * 2u;
        *(uint4*)(p + ao)        = make_uint4(h[0], h[1], h[2], h[3]);
        *(uint4*)(p + 5120 + ao) = make_uint4(l[0], l[1], l[2], l[3]);
    };

    loadA(0);
    if (t == 0) issueB(0);

    for (int ch = 0; ch < CH / BK; ++ch) {
        mbar_wait(mb_base + (uint32_t)(ch & 1) * 8, (uint32_t)((ch >> 1) & 1));
        storeA(ch);
        __syncthreads();   // all warps past compute(ch-1); A(ch)/B(ch) visible
        if (t == 0 && ch + 1 < CH / BK) issueB(ch + 1);
        if (ch + 1 < CH / BK) loadA(ch + 1);

        uint32_t abuf = sbase + (uint32_t)(ch & 1) * ABUF;
        uint32_t bbuf = sbase + BBASE + (uint32_t)(ch & 1) * BBUF;
        #pragma unroll
        for (int ks = 0; ks < BK; ks += 16) {
            uint32_t ah[2][4], al[2][4];
            #pragma unroll
            for (int i = 0; i < 2; ++i) {
                uint32_t mrow = (uint32_t)(wm * 32 + i * 16 + (lane & 15));
                uint32_t kcol = (uint32_t)(ks + (lane >> 4) * 8);
                uint32_t addr = abuf + mrow * 80u + kcol * 2u;
                LDSM4(ah[i], addr);
                LDSM4(al[i], addr + 5120u);
            }
            #pragma unroll
            for (int p = 0; p < 4; ++p) {
                uint32_t bh[4], bl[4];
                uint32_t krow = (uint32_t)(ks + (lane & 15));
                uint32_t gran = (uint32_t)(wn * 8 + p * 2 + (lane >> 4));
                uint32_t addr = bbuf + krow * 512u + ((gran ^ (krow & 7)) << 4);
                LDSM4T(bh, addr);
                LDSM4T(bl, addr + 16384u);
                #pragma unroll
                for (int i = 0; i < 2; ++i) {
                    MMA(acc[i][2 * p],     ah[i], bh[0], bh[1]);
                    MMA(acc[i][2 * p],     ah[i], bl[0], bl[1]);
                    MMA(acc[i][2 * p],     al[i], bh[0], bh[1]);
                    MMA(acc[i][2 * p + 1], ah[i], bh[2], bh[3]);
                    MMA(acc[i][2 * p + 1], ah[i], bl[2], bl[3]);
                    MMA(acc[i][2 * p + 1], al[i], bh[2], bh[3]);
                }
            }
        }
    }

    // epilogue
    #pragma unroll
    for (int i = 0; i < 2; ++i) {
        int row = m0 + wm * 32 + i * 16 + (lane >> 2);
        float* o0 = out + ((size_t)g * BSZ + row) * CH + wn * 64 + (lane & 3) * 2;
        #pragma unroll
        for (int j = 0; j < 8; ++j) {
            *(float2*)(o0 + j * 8)          = make_float2(acc[i][j][0], acc[i][j][1]);
            *(float2*)(o0 + 8 * CH + j * 8) = make_float2(acc[i][j][2], acc[i][j][3]);
        }
    }
}

// ---------------- entry ----------------------------------------------------
extern "C" void kernel_launch(void* const* d_in, const int* in_sizes, int n_in,
                              void* d_out, int out_size) {
    const float* x = (const float*)d_in[0];
    const float* w = (const float*)d_in[1];
    if (n_in >= 2 && in_sizes[0] < in_sizes[1]) {
        const float* tmp = x; x = w; w = tmp;
    }
    float* out = (float*)d_out;

    cudaFuncSetAttribute(main_mma, cudaFuncAttributeMaxDynamicSharedMemorySize,
                         SMEM_TOTAL);
    cudaFuncSetAttribute(g_mma, cudaFuncAttributeMaxDynamicSharedMemorySize, 65536);
    cudaFuncSetAttribute(q_mma, cudaFuncAttributeMaxDynamicSharedMemorySize, 65536);
    cudaFuncSetAttribute(y_kernel, cudaFuncAttributeMaxDynamicSharedMemorySize,
                         Y_SMEM_BYTES);
    cudaFuncSetAttribute(tinv_kernel, cudaFuncAttributeMaxDynamicSharedMemorySize,
                         TINV_SMEM);

    vsplit<<<GRP * CH * CH / 1024, 256>>>(w);

    dim3 ggrid(3, GRP);
    g_mma<<<ggrid, 256, 65536>>>();

    tinv_kernel<<<GRP, 256, TINV_SMEM>>>();

    dim3 ygrid(CH / 32, GRP);
    y_kernel<<<ygrid, 256, Y_SMEM_BYTES>>>(w);

    dim3 qgrid(4, GRP);
    q_mma<<<qgrid, 256, 65536>>>();

    dim3 mgrid(BSZ / BM, GRP);
    main_mma<<<mgrid, 256, SMEM_TOTAL>>>(x, out);
}

// round 15
// speedup vs baseline: 1.0723x; 1.0162x over previous
#include <cuda_runtime.h>
#include <cuda_bf16.h>
#include <cstdint>

#define GRP 16
#define BSZ 8192
#define CH  256

// ---------------- scratch (device globals; no allocation allowed) ----------
__device__ float g_Gu[GRP * 28 * 1024];         // strict-upper G blocks, packed
__device__ float g_Gd[GRP * 8 * 1024];          // diagonal G blocks
__device__ float g_Tinv[GRP * 8 * 1024];        // diag-block inverses of R
// V images for g_mma: [GRP][2 panels][8 kchunks][8192B] (32 krows x 256B, swz)
__device__ unsigned char g_Vg_h[GRP * 131072];
__device__ unsigned char g_Vg_l[GRP * 131072];
// V images for q_mma: [GRP][8 kchunks][256 rows][64B] (swz gran^((row>>1)&3))
__device__ unsigned char g_Vq_h[GRP * 131072];
__device__ unsigned char g_Vq_l[GRP * 131072];
// Y images (same layout as Vq)
__device__ unsigned char g_Yq_h[GRP * 131072];
__device__ unsigned char g_Yq_l[GRP * 131072];
// Q^T hi/lo pre-swizzled SMEM images: [GRP][8 chunks][16384B]
__device__ unsigned char g_Qhi_sw[GRP * 8 * 16384];
__device__ unsigned char g_Qlo_sw[GRP * 8 * 16384];

__device__ __forceinline__ uint32_t smem_u32(const void* p) {
    uint32_t a;
    asm("{ .reg .u64 t; cvta.to.shared.u64 t, %1; cvt.u32.u64 %0, t; }"
        : "=r"(a) : "l"(p));
    return a;
}

#define LDSM4(r, addr)                                                      \
    asm volatile("ldmatrix.sync.aligned.m8n8.x4.shared.b16 {%0,%1,%2,%3}, [%4];" \
                 : "=r"((r)[0]), "=r"((r)[1]), "=r"((r)[2]), "=r"((r)[3])   \
                 : "r"(addr))
#define LDSM4T(r, addr)                                                     \
    asm volatile("ldmatrix.sync.aligned.m8n8.x4.trans.shared.b16 {%0,%1,%2,%3}, [%4];" \
                 : "=r"((r)[0]), "=r"((r)[1]), "=r"((r)[2]), "=r"((r)[3])   \
                 : "r"(addr))
#define MMA(c, a, b0, b1)                                                   \
    asm volatile("mma.sync.aligned.m16n8k16.row.col.f32.bf16.bf16.f32 "     \
                 "{%0,%1,%2,%3}, {%4,%5,%6,%7}, {%8,%9}, {%0,%1,%2,%3};"    \
                 : "+f"((c)[0]), "+f"((c)[1]), "+f"((c)[2]), "+f"((c)[3])   \
                 : "r"((a)[0]), "r"((a)[1]), "r"((a)[2]), "r"((a)[3]),      \
                   "r"(b0), "r"(b1))
#define CP16(dst, src)                                                      \
    asm volatile("cp.async.cg.shared.global [%0], [%1], 16;"                \
                 :: "r"(dst), "l"(src) : "memory")
#define BULK(dst, src, bytes, mbar)                                         \
    asm volatile("cp.async.bulk.shared::cluster.global.mbarrier::complete_tx::bytes " \
                 "[%0], [%1], %2, [%3];"                                    \
                 :: "r"(dst), "l"(src), "r"(bytes), "r"(mbar) : "memory")
#define EXPECT_TX(mbar, bytes)                                              \
    asm volatile("mbarrier.arrive.expect_tx.shared.b64 _, [%0], %1;"        \
                 :: "r"(mbar), "r"(bytes) : "memory")
#define MBINIT(mbar)                                                        \
    asm volatile("mbarrier.init.shared.b64 [%0], 1;" :: "r"(mbar) : "memory")

__device__ __forceinline__ void mbar_wait(uint32_t mbar, uint32_t parity) {
    asm volatile(
        "{\n\t.reg .pred P;\n"
        "LW_%=:\n\t"
        "mbarrier.try_wait.parity.acquire.cta.shared::cta.b64 P, [%0], %1, 0x989680;\n\t"
        "@P bra LD_%=;\n\t"
        "bra LW_%=;\n"
        "LD_%=:\n\t}"
        :: "r"(mbar), "r"(parity) : "memory");
}

__device__ __forceinline__ uint32_t pack_hi(float a, float b) {
    __nv_bfloat16 x = __float2bfloat16(a), y = __float2bfloat16(b);
    return ((uint32_t)__bfloat16_as_ushort(y) << 16) | __bfloat16_as_ushort(x);
}
__device__ __forceinline__ uint32_t pack_lo(float a, float b) {
    __nv_bfloat16 x = __float2bfloat16(a), y = __float2bfloat16(b);
    __nv_bfloat16 lx = __float2bfloat16(a - __bfloat162float(x));
    __nv_bfloat16 ly = __float2bfloat16(b - __bfloat162float(y));
    return ((uint32_t)__bfloat16_as_ushort(ly) << 16) | __bfloat16_as_ushort(lx);
}

// ---------------- vsplit: W -> pre-swizzled hi/lo images (g & q layouts) ---
__global__ void vsplit(const float* __restrict__ W) {
    int idx4 = (blockIdx.x * 256 + threadIdx.x) * 4;
    int g = idx4 >> 16;
    int row = (idx4 >> 8) & 255, col = idx4 & 255;
    float4 v = *(const float4*)(W + idx4);
    uint2 h, l;
    h.x = pack_hi(v.x, v.y); h.y = pack_hi(v.z, v.w);
    l.x = pack_lo(v.x, v.y); l.y = pack_lo(v.z, v.w);
    // q layout
    {
        int chunk = col >> 5, c = col & 31, gran = c >> 3, sub = (c & 7) * 2;
        size_t off = (size_t)g * 131072 + chunk * 16384 + row * 64 +
                     ((gran ^ ((row >> 1) & 3)) << 4) + sub;
        *(uint2*)(g_Vq_h + off) = h;
        *(uint2*)(g_Vq_l + off) = l;
    }
    // g layout
    {
        int panel = col >> 7, cp = col & 127;
        int kch = row >> 5, kk = row & 31;
        int gr = cp >> 3, sg = (cp & 7) * 2;
        size_t off = (size_t)g * 131072 + panel * 65536 + kch * 8192 +
                     kk * 256 + ((gr ^ (kk & 7)) << 4) + sg;
        *(uint2*)(g_Vg_h + off) = h;
        *(uint2*)(g_Vg_l + off) = l;
    }
}

// ---------------- g_mma: G = V^T V (bulk-staged, packed-block output) ------
#define GSTRIDE 32768u
__global__ void __launch_bounds__(256) g_mma() {
    extern __shared__ __align__(1024) char sm[];
    __shared__ __align__(8) uint64_t mbars[2];
    const uint32_t sb = smem_u32(sm);
    const uint32_t mb = smem_u32(mbars);
    int t = threadIdx.x, warp = t >> 5, lane = t & 31;
    int wm = warp >> 2, wn = warp & 3;
    int g = blockIdx.y;
    int bx = blockIdx.x;                 // 0:(0,0) 1:(0,128) 2:(128,128)
    int a0 = (bx == 2) ? 128 : 0;
    int b0 = (bx == 0) ? 0 : 128;
    int pa = a0 >> 7, pb = b0 >> 7;

    const unsigned char* VAh = g_Vg_h + (size_t)g * 131072 + pa * 65536;
    const unsigned char* VAl = g_Vg_l + (size_t)g * 131072 + pa * 65536;
    const unsigned char* VBh = g_Vg_h + (size_t)g * 131072 + pb * 65536;
    const unsigned char* VBl = g_Vg_l + (size_t)g * 131072 + pb * 65536;

    if (t == 0) { MBINIT(mb); MBINIT(mb + 8); }
    __syncthreads();

    auto stage = [&](int ch) {   // t == 0 only
        uint32_t mbar = mb + (uint32_t)(ch & 1) * 8;
        uint32_t d = sb + (uint32_t)(ch & 1) * GSTRIDE;
        EXPECT_TX(mbar, 32768u);
        BULK(d,          VAh + ch * 8192, 8192u, mbar);
        BULK(d + 8192,   VAl + ch * 8192, 8192u, mbar);
        BULK(d + 16384,  VBh + ch * 8192, 8192u, mbar);
        BULK(d + 24576,  VBl + ch * 8192, 8192u, mbar);
    };

    float acc[4][4][4] = {};
    if (t == 0) stage(0);
    for (int ch = 0; ch < 8; ++ch) {
        mbar_wait(mb + (uint32_t)(ch & 1) * 8, (uint32_t)((ch >> 1) & 1));
        __syncthreads();
        if (t == 0 && ch < 7) stage(ch + 1);
        uint32_t buf = sb + (uint32_t)(ch & 1) * GSTRIDE;
        #pragma unroll
        for (int ks = 0; ks < 32; ks += 16) {
            uint32_t ah[4][4], al[4][4];
            #pragma unroll
            for (int i = 0; i < 4; ++i) {
                uint32_t mbcol = (uint32_t)(wm * 64 + i * 16);
                uint32_t krow = (uint32_t)(ks + (lane & 7) + ((lane >> 4) << 3));
                uint32_t gran = (mbcol >> 3) + ((lane >> 3) & 1);
                uint32_t addr = buf + krow * 256u + ((gran ^ (krow & 7)) << 4);
                LDSM4T(ah[i], addr);
                LDSM4T(al[i], addr + 8192);
            }
            #pragma unroll
            for (int p = 0; p < 2; ++p) {
                uint32_t bh[4], bl[4];
                uint32_t krow = (uint32_t)(ks + (lane & 15));
                uint32_t gran = (uint32_t)(wn * 4 + p * 2 + (lane >> 4));
                uint32_t addr = buf + 16384 + krow * 256u + ((gran ^ (krow & 7)) << 4);
                LDSM4T(bh, addr);
                LDSM4T(bl, addr + 8192);
                #pragma unroll
                for (int i = 0; i < 4; ++i) {
                    MMA(acc[i][2 * p],     ah[i], bh[0], bh[1]);
                    MMA(acc[i][2 * p],     ah[i], bl[0], bl[1]);
                    MMA(acc[i][2 * p],     al[i], bh[0], bh[1]);
                    MMA(acc[i][2 * p + 1], ah[i], bh[2], bh[3]);
                    MMA(acc[i][2 * p + 1], ah[i], bl[2], bl[3]);
                    MMA(acc[i][2 * p + 1], al[i], bh[2], bh[3]);
                }
            }
        }
    }
    // epilogue: packed strict-upper + diagonal block layout
    float* Gu = g_Gu + (size_t)g * 28 * 1024;
    float* Gd = g_Gd + (size_t)g * 8 * 1024;
    #pragma unroll
    for (int i = 0; i < 4; ++i) {
        int rowa = a0 + wm * 64 + i * 16 + (lane >> 2);
        #pragma unroll
        for (int j = 0; j < 4; ++j) {
            int colb = b0 + wn * 32 + j * 8 + (lane & 3) * 2;
            int kbb = colb >> 5;
            #pragma unroll
            for (int rh = 0; rh < 2; ++rh) {
                int row = rowa + rh * 8;
                int jcb = row >> 5;
                float2 v = make_float2(acc[i][j][2 * rh], acc[i][j][2 * rh + 1]);
                int boff = (row & 31) * 32 + (colb & 31);
                if (jcb < kbb)
                    *(float2*)&Gu[(kbb * (kbb - 1) / 2 + jcb) * 1024 + boff] = v;
                else if (jcb == kbb)
                    *(float2*)&Gd[kbb * 1024 + boff] = v;
            }
        }
    }
}

// ---------------- tinv: invert 32x32 diagonal blocks of R ------------------
#define TINV_SMEM ((8448 + 8448 + 256) * 4)
__global__ void __launch_bounds__(256) tinv_kernel() {
    extern __shared__ __align__(16) float S[];
    float* Gds = S;            // 8 blocks [32][33]
    float* Ts  = S + 8448;
    float* bet = S + 16896;

    int g = blockIdx.x;
    int t = threadIdx.x;
    const float* Gsrc = g_Gd + (size_t)g * 8 * 1024;

    for (int e = t; e < 8192; e += 256) {
        int kb = e >> 10, i = (e >> 5) & 31, k = e & 31;
        Gds[kb * 1056 + i * 33 + k] = Gsrc[kb * 1024 + i * 32 + k];
    }
    {
        int kb = t >> 5, j = t & 31;
        bet[t] = 2.0f / Gsrc[kb * 1024 + j * 32 + j];
    }
    __syncthreads();

    int kb = t >> 5, j = t & 31;
    int c0 = kb * 32;
    float* Tb = Ts + kb * 1056;
    const float* Gb = Gds + kb * 1056;
    for (int i = j + 1; i < 32; ++i) Tb[i * 33 + j] = 0.f;
    Tb[j * 33 + j] = bet[c0 + j];
    for (int i = j - 1; i >= 0; --i) {
        float s = 0.f;
        for (int k = i + 1; k <= j; ++k)
            s += Gb[i * 33 + k] * Tb[k * 33 + j];
        Tb[i * 33 + j] = -bet[c0 + i] * s;
    }
    __syncthreads();
    float* Tg = g_Tinv + ((size_t)g * 8 + kb) * 1024;
    for (int i = 0; i < 32; ++i)
        Tg[i * 32 + j] = Tb[i * 33 + j];
}

// ---------------- Y = V R^{-1}: bulk-loaded panel, warp-parallel -----------
#define YGU   0
#define YTD   28672
#define YYS   36864
#define YPRE  45312
#define YSP   46464
#define Y_SMEM_FLOATS 55680
#define Y_SMEM_BYTES  (Y_SMEM_FLOATS * 4)
__global__ void __launch_bounds__(256) y_kernel(const float* __restrict__ W) {
    extern __shared__ __align__(128) float S[];
    __shared__ __align__(8) uint64_t ymb[1];
    const uint32_t sb = smem_u32(S);
    const uint32_t mb = smem_u32(ymb);
    int g  = blockIdx.y;
    int r0 = blockIdx.x * 32;
    int t  = threadIdx.x;

    const float* Vg = W + (size_t)g * CH * CH;

    if (t == 0) MBINIT(mb);
    __syncthreads();
    if (t == 0) {
        EXPECT_TX(mb, 147456u);   // 2x57344 Gu + 32768 Td
        const unsigned char* GuS = (const unsigned char*)(g_Gu + (size_t)g * 28 * 1024);
        const unsigned char* TdS = (const unsigned char*)(g_Tinv + (size_t)g * 8 * 1024);
        BULK(sb + YGU * 4,          GuS,          57344u, mb);
        BULK(sb + YGU * 4 + 57344,  GuS + 57344,  57344u, mb);
        BULK(sb + YTD * 4,          TdS,          32768u, mb);
    }
    // V -> Ys init (small, scalar cp.async)
    {
        int rr = t >> 3, c = t & 7;
        for (int cc = c; cc < 64; cc += 8)
            CP16(sb + (uint32_t)(YYS + rr * 264 + cc * 4) * 4,
                 Vg + (size_t)(r0 + rr) * CH + cc * 4);
        asm volatile("cp.async.commit_group;" ::: "memory");
        asm volatile("cp.async.wait_group 0;" ::: "memory");
    }
    mbar_wait(mb, 0u);
    __syncthreads();

    int w = t >> 5, l = t & 31;
    int q = l & 7, r2 = l >> 3;
    int r = t >> 3, q8 = t & 7;

    for (int kb = 0; kb < 8; ++kb) {
        int c0 = kb * 32;
        float a[8][4] = {};
        int pbase = kb * (kb - 1) / 2;
        for (int jc = w; jc < kb; jc += 8) {
            const float* Gb = S + YGU + (pbase + jc) * 1024 + 4 * q;
            int j0 = jc * 32;
            #pragma unroll
            for (int jj = 0; jj < 32; ++jj) {
                float4 gg = *(const float4*)(Gb + jj * 32);
                #pragma unroll
                for (int ri = 0; ri < 8; ++ri) {
                    float yv = S[YYS + (r2 + 4 * ri) * 264 + j0 + jj];
                    a[ri][0] += yv * gg.x;
                    a[ri][1] += yv * gg.y;
                    a[ri][2] += yv * gg.z;
                    a[ri][3] += yv * gg.w;
                }
            }
        }
        #pragma unroll
        for (int ri = 0; ri < 8; ++ri) {
            float4 v = {a[ri][0], a[ri][1], a[ri][2], a[ri][3]};
            *(float4*)(S + YSP + w * 1152 + (r2 + 4 * ri) * 36 + 4 * q) = v;
        }
        __syncthreads();
        float4 pr = *(const float4*)(S + YYS + r * 264 + c0 + 4 * q8);
        #pragma unroll
        for (int w2 = 0; w2 < 8; ++w2) {
            float4 s = *(const float4*)(S + YSP + w2 * 1152 + r * 36 + 4 * q8);
            pr.x -= s.x; pr.y -= s.y; pr.z -= s.z; pr.w -= s.w;
        }
        *(float4*)(S + YPRE + r * 36 + 4 * q8) = pr;
        __syncwarp();
        const float* Tdb = S + YTD + kb * 1024 + 4 * q8;
        float o0 = 0.f, o1 = 0.f, o2 = 0.f, o3 = 0.f;
        #pragma unroll
        for (int i = 0; i < 32; ++i) {
            float pv = S[YPRE + r * 36 + i];
            float4 tv = *(const float4*)(Tdb + i * 32);
            o0 += pv * tv.x;
            o1 += pv * tv.y;
            o2 += pv * tv.z;
            o3 += pv * tv.w;
        }
        float4 ov = {o0, o1, o2, o3};
        *(float4*)(S + YYS + r * 264 + c0 + 4 * q8) = ov;
        __syncthreads();
    }

    // emit Y into q-friendly pre-swizzled images
    unsigned char* Yh = g_Yq_h + (size_t)g * 131072;
    unsigned char* Yl = g_Yq_l + (size_t)g * 131072;
    for (int e = t; e < 32 * (CH / 2); e += 256) {
        int rr = e >> 7, cc = (e & 127) * 2;
        float v0 = S[YYS + rr * 264 + cc], v1 = S[YYS + rr * 264 + cc + 1];
        int grow = r0 + rr;
        int chunk = cc >> 5, c = cc & 31, gran = c >> 3, sub = (c & 7) * 2;
        size_t off = (size_t)chunk * 16384 + grow * 64 +
                     ((gran ^ ((grow >> 1) & 3)) << 4) + sub;
        *(uint32_t*)(Yh + off) = pack_hi(v0, v1);
        *(uint32_t*)(Yl + off) = pack_lo(v0, v1);
    }
}

// ---------------- q_mma: Q = I - Y V^T (bulk-staged) -----------------------
#define QSTRIDE 32768u
__global__ void __launch_bounds__(256) q_mma() {
    extern __shared__ __align__(1024) char sm[];
    __shared__ __align__(8) uint64_t mbars[2];
    const uint32_t sb = smem_u32(sm);
    const uint32_t mb = smem_u32(mbars);
    int t = threadIdx.x, warp = t >> 5, lane = t & 31;
    int wm = warp >> 2, wn = warp & 3;
    int g = blockIdx.y;
    int a0 = (blockIdx.x >> 1) * 128, b0 = (blockIdx.x & 1) * 128;

    const unsigned char* Yh = g_Yq_h + (size_t)g * 131072;
    const unsigned char* Yl = g_Yq_l + (size_t)g * 131072;
    const unsigned char* Vh = g_Vq_h + (size_t)g * 131072;
    const unsigned char* Vl = g_Vq_l + (size_t)g * 131072;

    if (t == 0) { MBINIT(mb); MBINIT(mb + 8); }
    __syncthreads();

    auto stage = [&](int ch) {   // t == 0 only
        uint32_t mbar = mb + (uint32_t)(ch & 1) * 8;
        uint32_t d = sb + (uint32_t)(ch & 1) * QSTRIDE;
        EXPECT_TX(mbar, 32768u);
        BULK(d,         Yh + (size_t)ch * 16384 + a0 * 64, 8192u, mbar);
        BULK(d + 8192,  Yl + (size_t)ch * 16384 + a0 * 64, 8192u, mbar);
        BULK(d + 16384, Vh + (size_t)ch * 16384 + b0 * 64, 8192u, mbar);
        BULK(d + 24576, Vl + (size_t)ch * 16384 + b0 * 64, 8192u, mbar);
    };

    float acc[4][4][4] = {};
    if (t == 0) stage(0);
    for (int ch = 0; ch < 8; ++ch) {
        mbar_wait(mb + (uint32_t)(ch & 1) * 8, (uint32_t)((ch >> 1) & 1));
        __syncthreads();
        if (t == 0 && ch < 7) stage(ch + 1);
        uint32_t buf = sb + (uint32_t)(ch & 1) * QSTRIDE;
        #pragma unroll
        for (int ks = 0; ks < 32; ks += 16) {
            uint32_t ah[4][4], al[4][4];
            #pragma unroll
            for (int i = 0; i < 4; ++i) {
                uint32_t mrow = (uint32_t)(wm * 64 + i * 16 + (lane & 15));
                uint32_t gran = (uint32_t)((ks >> 3) + (lane >> 4));
                uint32_t addr = buf + mrow * 64u + ((gran ^ ((mrow >> 1) & 3)) << 4);
                LDSM4(ah[i], addr);
                LDSM4(al[i], addr + 8192);
            }
            #pragma unroll
            for (int p = 0; p < 2; ++p) {
                uint32_t bh[4], bl[4];
                uint32_t nrow = (uint32_t)(wn * 32 + p * 16 + (lane & 7) + ((lane >> 4) << 3));
                uint32_t gran = (uint32_t)((ks >> 3) + ((lane >> 3) & 1));
                uint32_t addr = buf + 16384 + nrow * 64u + ((gran ^ ((nrow >> 1) & 3)) << 4);
                LDSM4(bh, addr);
                LDSM4(bl, addr + 8192);
                #pragma unroll
                for (int i = 0; i < 4; ++i) {
                    MMA(acc[i][2 * p],     ah[i], bh[0], bh[1]);
                    MMA(acc[i][2 * p],     ah[i], bl[0], bl[1]);
                    MMA(acc[i][2 * p],     al[i], bh[0], bh[1]);
                    MMA(acc[i][2 * p + 1], ah[i], bh[2], bh[3]);
                    MMA(acc[i][2 * p + 1], ah[i], bl[2], bl[3]);
                    MMA(acc[i][2 * p + 1], al[i], bh[2], bh[3]);
                }
            }
        }
    }
    // epilogue: write swizzled global Q images
    unsigned char* QH = g_Qhi_sw + (size_t)g * 8 * 16384;
    unsigned char* QL = g_Qlo_sw + (size_t)g * 8 * 16384;
    #pragma unroll
    for (int i = 0; i < 4; ++i) {
        int rr = a0 + wm * 64 + i * 16 + (lane >> 2);
        #pragma unroll
        for (int j = 0; j < 4; ++j) {
            int cc = b0 + wn * 32 + j * 8 + (lane & 3) * 2;
            float v0 = (rr == cc     ? 1.f : 0.f) - acc[i][j][0];
            float v1 = (rr == cc + 1 ? 1.f : 0.f) - acc[i][j][1];
            float v2 = (rr + 8 == cc     ? 1.f : 0.f) - acc[i][j][2];
            float v3 = (rr + 8 == cc + 1 ? 1.f : 0.f) - acc[i][j][3];
            int gran = cc >> 3, sub = (cc & 7) * 2;
            #pragma unroll
            for (int rh = 0; rh < 2; ++rh) {
                int k = rr + rh * 8;
                int chunk = k >> 5, krw = k & 31;
                size_t off = (size_t)chunk * 16384 + krw * 512 +
                             ((gran ^ (krw & 7)) << 4) + sub;
                *(uint32_t*)(QH + off) = pack_hi(rh ? v2 : v0, rh ? v3 : v1);
                *(uint32_t*)(QL + off) = pack_lo(rh ? v2 : v0, rh ? v3 : v1);
            }
        }
    }
}

// ---------------- out = x @ Q: BM=64, 2 CTAs/SM, bulk-B double buffer ------
#define BM 64
#define BN 256
#define BK 32
#define ABUF 10240u
#define BBASE 20480u
#define BBUF 32768u
#define SMEM_TOTAL (BBASE + 2u * BBUF)   // 86016

__global__ void __launch_bounds__(256, 2) main_mma(const float* __restrict__ X,
                                                   float* __restrict__ out) {
    extern __shared__ __align__(1024) char sm[];
    __shared__ __align__(8) uint64_t mbars[2];
    const uint32_t sbase = smem_u32(sm);
    const uint32_t mb_base = smem_u32(mbars);

    int t = threadIdx.x;
    int warp = t >> 5, lane = t & 31;
    int wm = warp >> 2, wn = warp & 3;      // warp tile 32m x 64n
    int g = blockIdx.y;
    int m0 = blockIdx.x * BM;

    const float* Xg = X + ((size_t)g * BSZ + m0) * CH;
    const unsigned char* QH = g_Qhi_sw + (size_t)g * 8 * 16384;
    const unsigned char* QL = g_Qlo_sw + (size_t)g * 8 * 16384;

    if (t == 0) { MBINIT(mb_base); MBINIT(mb_base + 8); }
    __syncthreads();

    int ar = t >> 2, ac = (t & 3) * 8;

    float acc[2][8][4] = {};
    float4 xa[2];

    auto loadA = [&](int ch) {
        xa[0] = *(const float4*)(Xg + (size_t)ar * CH + ch * BK + ac);
        xa[1] = *(const float4*)(Xg + (size_t)ar * CH + ch * BK + ac + 4);
    };
    auto issueB = [&](int ch) {   // t == 0 only
        int b = ch & 1;
        uint32_t mbar = mb_base + (uint32_t)b * 8;
        uint32_t dH = sbase + BBASE + (uint32_t)b * BBUF;
        EXPECT_TX(mbar, 32768u);
        BULK(dH,          QH + (size_t)ch * 16384, 16384u, mbar);
        BULK(dH + 16384,  QL + (size_t)ch * 16384, 16384u, mbar);
    };
    auto storeA = [&](int ch) {
        char* p = sm + (ch & 1) * ABUF;
        float f[8] = {xa[0].x, xa[0].y, xa[0].z, xa[0].w,
                      xa[1].x, xa[1].y, xa[1].z, xa[1].w};
        uint32_t h[4], l[4];
        #pragma unroll
        for (int i = 0; i < 4; ++i) {
            h[i] = pack_hi(f[2 * i], f[2 * i + 1]);
            l[i] = pack_lo(f[2 * i], f[2 * i + 1]);
        }
        uint32_t ao = ar * 80u + ac * 2u;
        *(uint4*)(p + ao)        = make_uint4(h[0], h[1], h[2], h[3]);
        *(uint4*)(p + 5120 + ao) = make_uint4(l[0], l[1], l[2], l[3]);
    };

    loadA(0);
    if (t == 0) issueB(0);

    for (int ch = 0; ch < CH / BK; ++ch) {
        mbar_wait(mb_base + (uint32_t)(ch & 1) * 8, (uint32_t)((ch >> 1) & 1));
        storeA(ch);
        __syncthreads();
        if (t == 0 && ch + 1 < CH / BK) issueB(ch + 1);
        if (ch + 1 < CH / BK) loadA(ch + 1);

        uint32_t abuf = sbase + (uint32_t)(ch & 1) * ABUF;
        uint32_t bbuf = sbase + BBASE + (uint32_t)(ch & 1) * BBUF;
        #pragma unroll
        for (int ks = 0; ks < BK; ks += 16) {
            uint32_t ah[2][4], al[2][4];
            #pragma unroll
            for (int i = 0; i < 2; ++i) {
                uint32_t mrow = (uint32_t)(wm * 32 + i * 16 + (lane & 15));
                uint32_t kcol = (uint32_t)(ks + (lane >> 4) * 8);
                uint32_t addr = abuf + mrow * 80u + kcol * 2u;
                LDSM4(ah[i], addr);
                LDSM4(al[i], addr + 5120u);
            }
            #pragma unroll
            for (int p = 0; p < 4; ++p) {
                uint32_t bh[4], bl[4];
                uint32_t krow = (uint32_t)(ks + (lane & 15));
                uint32_t gran = (uint32_t)(wn * 8 + p * 2 + (lane >> 4));
                uint32_t addr = bbuf + krow * 512u + ((gran ^ (krow & 7)) << 4);
                LDSM4T(bh, addr);
                LDSM4T(bl, addr + 16384u);
                #pragma unroll
                for (int i = 0; i < 2; ++i) {
                    MMA(acc[i][2 * p],     ah[i], bh[0], bh[1]);
                    MMA(acc[i][2 * p],     ah[i], bl[0], bl[1]);
                    MMA(acc[i][2 * p],     al[i], bh[0], bh[1]);
                    MMA(acc[i][2 * p + 1], ah[i], bh[2], bh[3]);
                    MMA(acc[i][2 * p + 1], ah[i], bl[2], bl[3]);
                    MMA(acc[i][2 * p + 1], al[i], bh[2], bh[3]);
                }
            }
        }
    }

    // epilogue
    #pragma unroll
    for (int i = 0; i < 2; ++i) {
        int row = m0 + wm * 32 + i * 16 + (lane >> 2);
        float* o0 = out + ((size_t)g * BSZ + row) * CH + wn * 64 + (lane & 3) * 2;
        #pragma unroll
        for (int j = 0; j < 8; ++j) {
            *(float2*)(o0 + j * 8)          = make_float2(acc[i][j][0], acc[i][j][1]);
            *(float2*)(o0 + 8 * CH + j * 8) = make_float2(acc[i][j][2], acc[i][j][3]);
        }
    }
}

// ---------------- entry ----------------------------------------------------
extern "C" void kernel_launch(void* const* d_in, const int* in_sizes, int n_in,
                              void* d_out, int out_size) {
    const float* x = (const float*)d_in[0];
    const float* w = (const float*)d_in[1];
    if (n_in >= 2 && in_sizes[0] < in_sizes[1]) {
        const float* tmp = x; x = w; w = tmp;
    }
    float* out = (float*)d_out;

    cudaFuncSetAttribute(main_mma, cudaFuncAttributeMaxDynamicSharedMemorySize,
                         SMEM_TOTAL);
    cudaFuncSetAttribute(g_mma, cudaFuncAttributeMaxDynamicSharedMemorySize, 65536);
    cudaFuncSetAttribute(q_mma, cudaFuncAttributeMaxDynamicSharedMemorySize, 65536);
    cudaFuncSetAttribute(y_kernel, cudaFuncAttributeMaxDynamicSharedMemorySize,
                         Y_SMEM_BYTES);
    cudaFuncSetAttribute(tinv_kernel, cudaFuncAttributeMaxDynamicSharedMemorySize,
                         TINV_SMEM);

    vsplit<<<GRP * CH * CH / 1024, 256>>>(w);

    dim3 ggrid(3, GRP);
    g_mma<<<ggrid, 256, 65536>>>();

    tinv_kernel<<<GRP, 256, TINV_SMEM>>>();

    dim3 ygrid(CH / 32, GRP);
    y_kernel<<<ygrid, 256, Y_SMEM_BYTES>>>(w);

    dim3 qgrid(4, GRP);
    q_mma<<<qgrid, 256, 65536>>>();

    dim3 mgrid(BSZ / BM, GRP);
    main_mma<<<mgrid, 256, SMEM_TOTAL>>>(x, out);
}

// round 16
// speedup vs baseline: 1.3145x; 1.2258x over previous
#include <cuda_runtime.h>
#include <cuda_bf16.h>
#include <cuda_fp16.h>
#include <cstdint>

#define GRP 16
#define BSZ 8192
#define CH  256

// ---------------- scratch (device globals; no allocation allowed) ----------
__device__ float g_Gu[GRP * 28 * 1024];         // strict-upper G blocks, packed
__device__ float g_Gd[GRP * 8 * 1024];          // diagonal G blocks
__device__ float g_Tinv[GRP * 8 * 1024];        // diag-block inverses of R
// V images for g_mma: [GRP][2 panels][8 kchunks][8192B] (32 krows x 256B, swz)
__device__ unsigned char g_Vg_h[GRP * 131072];
__device__ unsigned char g_Vg_l[GRP * 131072];
// V images for q_mma: [GRP][8 kchunks][256 rows][64B] (swz gran^((row>>1)&3))
__device__ unsigned char g_Vq_h[GRP * 131072];
__device__ unsigned char g_Vq_l[GRP * 131072];
// Y images (same layout as Vq)
__device__ unsigned char g_Yq_h[GRP * 131072];
__device__ unsigned char g_Yq_l[GRP * 131072];
// Q^T as single-fp16 pre-swizzled SMEM images: [GRP][8 chunks][16384B]
__device__ unsigned char g_Qf_sw[GRP * 8 * 16384];

__device__ __forceinline__ uint32_t smem_u32(const void* p) {
    uint32_t a;
    asm("{ .reg .u64 t; cvta.to.shared.u64 t, %1; cvt.u32.u64 %0, t; }"
        : "=r"(a) : "l"(p));
    return a;
}

#define LDSM4(r, addr)                                                      \
    asm volatile("ldmatrix.sync.aligned.m8n8.x4.shared.b16 {%0,%1,%2,%3}, [%4];" \
                 : "=r"((r)[0]), "=r"((r)[1]), "=r"((r)[2]), "=r"((r)[3])   \
                 : "r"(addr))
#define LDSM4T(r, addr)                                                     \
    asm volatile("ldmatrix.sync.aligned.m8n8.x4.trans.shared.b16 {%0,%1,%2,%3}, [%4];" \
                 : "=r"((r)[0]), "=r"((r)[1]), "=r"((r)[2]), "=r"((r)[3])   \
                 : "r"(addr))
#define MMA(c, a, b0, b1)                                                   \
    asm volatile("mma.sync.aligned.m16n8k16.row.col.f32.bf16.bf16.f32 "     \
                 "{%0,%1,%2,%3}, {%4,%5,%6,%7}, {%8,%9}, {%0,%1,%2,%3};"    \
                 : "+f"((c)[0]), "+f"((c)[1]), "+f"((c)[2]), "+f"((c)[3])   \
                 : "r"((a)[0]), "r"((a)[1]), "r"((a)[2]), "r"((a)[3]),      \
                   "r"(b0), "r"(b1))
#define MMAH(c, a, b0, b1)                                                  \
    asm volatile("mma.sync.aligned.m16n8k16.row.col.f32.f16.f16.f32 "       \
                 "{%0,%1,%2,%3}, {%4,%5,%6,%7}, {%8,%9}, {%0,%1,%2,%3};"    \
                 : "+f"((c)[0]), "+f"((c)[1]), "+f"((c)[2]), "+f"((c)[3])   \
                 : "r"((a)[0]), "r"((a)[1]), "r"((a)[2]), "r"((a)[3]),      \
                   "r"(b0), "r"(b1))
#define CP16(dst, src)                                                      \
    asm volatile("cp.async.cg.shared.global [%0], [%1], 16;"                \
                 :: "r"(dst), "l"(src) : "memory")
#define BULK(dst, src, bytes, mbar)                                         \
    asm volatile("cp.async.bulk.shared::cluster.global.mbarrier::complete_tx::bytes " \
                 "[%0], [%1], %2, [%3];"                                    \
                 :: "r"(dst), "l"(src), "r"(bytes), "r"(mbar) : "memory")
#define EXPECT_TX(mbar, bytes)                                              \
    asm volatile("mbarrier.arrive.expect_tx.shared.b64 _, [%0], %1;"        \
                 :: "r"(mbar), "r"(bytes) : "memory")
#define MBINIT(mbar)                                                        \
    asm volatile("mbarrier.init.shared.b64 [%0], 1;" :: "r"(mbar) : "memory")

__device__ __forceinline__ void mbar_wait(uint32_t mbar, uint32_t parity) {
    asm volatile(
        "{\n\t.reg .pred P;\n"
        "LW_%=:\n\t"
        "mbarrier.try_wait.parity.acquire.cta.shared::cta.b64 P, [%0], %1, 0x989680;\n\t"
        "@P bra LD_%=;\n\t"
        "bra LW_%=;\n"
        "LD_%=:\n\t}"
        :: "r"(mbar), "r"(parity) : "memory");
}

__device__ __forceinline__ uint32_t pack_hi(float a, float b) {
    __nv_bfloat16 x = __float2bfloat16(a), y = __float2bfloat16(b);
    return ((uint32_t)__bfloat16_as_ushort(y) << 16) | __bfloat16_as_ushort(x);
}
__device__ __forceinline__ uint32_t pack_lo(float a, float b) {
    __nv_bfloat16 x = __float2bfloat16(a), y = __float2bfloat16(b);
    __nv_bfloat16 lx = __float2bfloat16(a - __bfloat162float(x));
    __nv_bfloat16 ly = __float2bfloat16(b - __bfloat162float(y));
    return ((uint32_t)__bfloat16_as_ushort(ly) << 16) | __bfloat16_as_ushort(lx);
}
__device__ __forceinline__ uint32_t pack_f16(float a, float b) {
    __half x = __float2half_rn(a), y = __float2half_rn(b);
    return ((uint32_t)__half_as_ushort(y) << 16) | __half_as_ushort(x);
}
__device__ __forceinline__ uint32_t pack_f16lo(float a, float b) {
    __half x = __float2half_rn(a), y = __float2half_rn(b);
    __half lx = __float2half_rn(a - __half2float(x));
    __half ly = __float2half_rn(b - __half2float(y));
    return ((uint32_t)__half_as_ushort(ly) << 16) | __half_as_ushort(lx);
}

// ---------------- vsplit: W -> pre-swizzled hi/lo images (g & q layouts) ---
__global__ void vsplit(const float* __restrict__ W) {
    int idx4 = (blockIdx.x * 256 + threadIdx.x) * 4;
    int g = idx4 >> 16;
    int row = (idx4 >> 8) & 255, col = idx4 & 255;
    float4 v = *(const float4*)(W + idx4);
    uint2 h, l;
    h.x = pack_hi(v.x, v.y); h.y = pack_hi(v.z, v.w);
    l.x = pack_lo(v.x, v.y); l.y = pack_lo(v.z, v.w);
    // q layout
    {
        int chunk = col >> 5, c = col & 31, gran = c >> 3, sub = (c & 7) * 2;
        size_t off = (size_t)g * 131072 + chunk * 16384 + row * 64 +
                     ((gran ^ ((row >> 1) & 3)) << 4) + sub;
        *(uint2*)(g_Vq_h + off) = h;
        *(uint2*)(g_Vq_l + off) = l;
    }
    // g layout
    {
        int panel = col >> 7, cp = col & 127;
        int kch = row >> 5, kk = row & 31;
        int gr = cp >> 3, sg = (cp & 7) * 2;
        size_t off = (size_t)g * 131072 + panel * 65536 + kch * 8192 +
                     kk * 256 + ((gr ^ (kk & 7)) << 4) + sg;
        *(uint2*)(g_Vg_h + off) = h;
        *(uint2*)(g_Vg_l + off) = l;
    }
}

// ---------------- g_mma: G = V^T V (bulk-staged, packed-block output) ------
#define GSTRIDE 32768u
__global__ void __launch_bounds__(256) g_mma() {
    extern __shared__ __align__(1024) char sm[];
    __shared__ __align__(8) uint64_t mbars[2];
    const uint32_t sb = smem_u32(sm);
    const uint32_t mb = smem_u32(mbars);
    int t = threadIdx.x, warp = t >> 5, lane = t & 31;
    int wm = warp >> 2, wn = warp & 3;
    int g = blockIdx.y;
    int bx = blockIdx.x;                 // 0:(0,0) 1:(0,128) 2:(128,128)
    int a0 = (bx == 2) ? 128 : 0;
    int b0 = (bx == 0) ? 0 : 128;
    int pa = a0 >> 7, pb = b0 >> 7;

    const unsigned char* VAh = g_Vg_h + (size_t)g * 131072 + pa * 65536;
    const unsigned char* VAl = g_Vg_l + (size_t)g * 131072 + pa * 65536;
    const unsigned char* VBh = g_Vg_h + (size_t)g * 131072 + pb * 65536;
    const unsigned char* VBl = g_Vg_l + (size_t)g * 131072 + pb * 65536;

    if (t == 0) { MBINIT(mb); MBINIT(mb + 8); }
    __syncthreads();

    auto stage = [&](int ch) {   // t == 0 only
        uint32_t mbar = mb + (uint32_t)(ch & 1) * 8;
        uint32_t d = sb + (uint32_t)(ch & 1) * GSTRIDE;
        EXPECT_TX(mbar, 32768u);
        BULK(d,          VAh + ch * 8192, 8192u, mbar);
        BULK(d + 8192,   VAl + ch * 8192, 8192u, mbar);
        BULK(d + 16384,  VBh + ch * 8192, 8192u, mbar);
        BULK(d + 24576,  VBl + ch * 8192, 8192u, mbar);
    };

    float acc[4][4][4] = {};
    if (t == 0) stage(0);
    for (int ch = 0; ch < 8; ++ch) {
        mbar_wait(mb + (uint32_t)(ch & 1) * 8, (uint32_t)((ch >> 1) & 1));
        __syncthreads();
        if (t == 0 && ch < 7) stage(ch + 1);
        uint32_t buf = sb + (uint32_t)(ch & 1) * GSTRIDE;
        #pragma unroll
        for (int ks = 0; ks < 32; ks += 16) {
            uint32_t ah[4][4], al[4][4];
            #pragma unroll
            for (int i = 0; i < 4; ++i) {
                uint32_t mbcol = (uint32_t)(wm * 64 + i * 16);
                uint32_t krow = (uint32_t)(ks + (lane & 7) + ((lane >> 4) << 3));
                uint32_t gran = (mbcol >> 3) + ((lane >> 3) & 1);
                uint32_t addr = buf + krow * 256u + ((gran ^ (krow & 7)) << 4);
                LDSM4T(ah[i], addr);
                LDSM4T(al[i], addr + 8192);
            }
            #pragma unroll
            for (int p = 0; p < 2; ++p) {
                uint32_t bh[4], bl[4];
                uint32_t krow = (uint32_t)(ks + (lane & 15));
                uint32_t gran = (uint32_t)(wn * 4 + p * 2 + (lane >> 4));
                uint32_t addr = buf + 16384 + krow * 256u + ((gran ^ (krow & 7)) << 4);
                LDSM4T(bh, addr);
                LDSM4T(bl, addr + 8192);
                #pragma unroll
                for (int i = 0; i < 4; ++i) {
                    MMA(acc[i][2 * p],     ah[i], bh[0], bh[1]);
                    MMA(acc[i][2 * p],     ah[i], bl[0], bl[1]);
                    MMA(acc[i][2 * p],     al[i], bh[0], bh[1]);
                    MMA(acc[i][2 * p + 1], ah[i], bh[2], bh[3]);
                    MMA(acc[i][2 * p + 1], ah[i], bl[2], bl[3]);
                    MMA(acc[i][2 * p + 1], al[i], bh[2], bh[3]);
                }
            }
        }
    }
    // epilogue: packed strict-upper + diagonal block layout
    float* Gu = g_Gu + (size_t)g * 28 * 1024;
    float* Gd = g_Gd + (size_t)g * 8 * 1024;
    #pragma unroll
    for (int i = 0; i < 4; ++i) {
        int rowa = a0 + wm * 64 + i * 16 + (lane >> 2);
        #pragma unroll
        for (int j = 0; j < 4; ++j) {
            int colb = b0 + wn * 32 + j * 8 + (lane & 3) * 2;
            int kbb = colb >> 5;
            #pragma unroll
            for (int rh = 0; rh < 2; ++rh) {
                int row = rowa + rh * 8;
                int jcb = row >> 5;
                float2 v = make_float2(acc[i][j][2 * rh], acc[i][j][2 * rh + 1]);
                int boff = (row & 31) * 32 + (colb & 31);
                if (jcb < kbb)
                    *(float2*)&Gu[(kbb * (kbb - 1) / 2 + jcb) * 1024 + boff] = v;
                else if (jcb == kbb)
                    *(float2*)&Gd[kbb * 1024 + boff] = v;
            }
        }
    }
}

// ---------------- tinv: invert 32x32 diagonal blocks of R ------------------
#define TINV_SMEM ((8448 + 8448 + 256) * 4)
__global__ void __launch_bounds__(256) tinv_kernel() {
    extern __shared__ __align__(16) float S[];
    float* Gds = S;
    float* Ts  = S + 8448;
    float* bet = S + 16896;

    int g = blockIdx.x;
    int t = threadIdx.x;
    const float* Gsrc = g_Gd + (size_t)g * 8 * 1024;

    for (int e = t; e < 8192; e += 256) {
        int kb = e >> 10, i = (e >> 5) & 31, k = e & 31;
        Gds[kb * 1056 + i * 33 + k] = Gsrc[kb * 1024 + i * 32 + k];
    }
    {
        int kb = t >> 5, j = t & 31;
        bet[t] = 2.0f / Gsrc[kb * 1024 + j * 32 + j];
    }
    __syncthreads();

    int kb = t >> 5, j = t & 31;
    int c0 = kb * 32;
    float* Tb = Ts + kb * 1056;
    const float* Gb = Gds + kb * 1056;
    for (int i = j + 1; i < 32; ++i) Tb[i * 33 + j] = 0.f;
    Tb[j * 33 + j] = bet[c0 + j];
    for (int i = j - 1; i >= 0; --i) {
        float s = 0.f;
        for (int k = i + 1; k <= j; ++k)
            s += Gb[i * 33 + k] * Tb[k * 33 + j];
        Tb[i * 33 + j] = -bet[c0 + i] * s;
    }
    __syncthreads();
    float* Tg = g_Tinv + ((size_t)g * 8 + kb) * 1024;
    for (int i = 0; i < 32; ++i)
        Tg[i * 32 + j] = Tb[i * 33 + j];
}

// ---------------- Y = V R^{-1}: bulk-loaded panel, warp-parallel -----------
#define YGU   0
#define YTD   28672
#define YYS   36864
#define YPRE  45312
#define YSP   46464
#define Y_SMEM_FLOATS 55680
#define Y_SMEM_BYTES  (Y_SMEM_FLOATS * 4)
__global__ void __launch_bounds__(256) y_kernel(const float* __restrict__ W) {
    extern __shared__ __align__(128) float S[];
    __shared__ __align__(8) uint64_t ymb[1];
    const uint32_t sb = smem_u32(S);
    const uint32_t mb = smem_u32(ymb);
    int g  = blockIdx.y;
    int r0 = blockIdx.x * 32;
    int t  = threadIdx.x;

    const float* Vg = W + (size_t)g * CH * CH;

    if (t == 0) MBINIT(mb);
    __syncthreads();
    if (t == 0) {
        EXPECT_TX(mb, 147456u);
        const unsigned char* GuS = (const unsigned char*)(g_Gu + (size_t)g * 28 * 1024);
        const unsigned char* TdS = (const unsigned char*)(g_Tinv + (size_t)g * 8 * 1024);
        BULK(sb + YGU * 4,          GuS,          57344u, mb);
        BULK(sb + YGU * 4 + 57344,  GuS + 57344,  57344u, mb);
        BULK(sb + YTD * 4,          TdS,          32768u, mb);
    }
    {
        int rr = t >> 3, c = t & 7;
        for (int cc = c; cc < 64; cc += 8)
            CP16(sb + (uint32_t)(YYS + rr * 264 + cc * 4) * 4,
                 Vg + (size_t)(r0 + rr) * CH + cc * 4);
        asm volatile("cp.async.commit_group;" ::: "memory");
        asm volatile("cp.async.wait_group 0;" ::: "memory");
    }
    mbar_wait(mb, 0u);
    __syncthreads();

    int w = t >> 5, l = t & 31;
    int q = l & 7, r2 = l >> 3;
    int r = t >> 3, q8 = t & 7;

    for (int kb = 0; kb < 8; ++kb) {
        int c0 = kb * 32;
        float a[8][4] = {};
        int pbase = kb * (kb - 1) / 2;
        for (int jc = w; jc < kb; jc += 8) {
            const float* Gb = S + YGU + (pbase + jc) * 1024 + 4 * q;
            int j0 = jc * 32;
            #pragma unroll
            for (int jj = 0; jj < 32; ++jj) {
                float4 gg = *(const float4*)(Gb + jj * 32);
                #pragma unroll
                for (int ri = 0; ri < 8; ++ri) {
                    float yv = S[YYS + (r2 + 4 * ri) * 264 + j0 + jj];
                    a[ri][0] += yv * gg.x;
                    a[ri][1] += yv * gg.y;
                    a[ri][2] += yv * gg.z;
                    a[ri][3] += yv * gg.w;
                }
            }
        }
        #pragma unroll
        for (int ri = 0; ri < 8; ++ri) {
            float4 v = {a[ri][0], a[ri][1], a[ri][2], a[ri][3]};
            *(float4*)(S + YSP + w * 1152 + (r2 + 4 * ri) * 36 + 4 * q) = v;
        }
        __syncthreads();
        float4 pr = *(const float4*)(S + YYS + r * 264 + c0 + 4 * q8);
        #pragma unroll
        for (int w2 = 0; w2 < 8; ++w2) {
            float4 s = *(const float4*)(S + YSP + w2 * 1152 + r * 36 + 4 * q8);
            pr.x -= s.x; pr.y -= s.y; pr.z -= s.z; pr.w -= s.w;
        }
        *(float4*)(S + YPRE + r * 36 + 4 * q8) = pr;
        __syncwarp();
        const float* Tdb = S + YTD + kb * 1024 + 4 * q8;
        float o0 = 0.f, o1 = 0.f, o2 = 0.f, o3 = 0.f;
        #pragma unroll
        for (int i = 0; i < 32; ++i) {
            float pv = S[YPRE + r * 36 + i];
            float4 tv = *(const float4*)(Tdb + i * 32);
            o0 += pv * tv.x;
            o1 += pv * tv.y;
            o2 += pv * tv.z;
            o3 += pv * tv.w;
        }
        float4 ov = {o0, o1, o2, o3};
        *(float4*)(S + YYS + r * 264 + c0 + 4 * q8) = ov;
        __syncthreads();
    }

    // emit Y into q-friendly pre-swizzled images
    unsigned char* Yh = g_Yq_h + (size_t)g * 131072;
    unsigned char* Yl = g_Yq_l + (size_t)g * 131072;
    for (int e = t; e < 32 * (CH / 2); e += 256) {
        int rr = e >> 7, cc = (e & 127) * 2;
        float v0 = S[YYS + rr * 264 + cc], v1 = S[YYS + rr * 264 + cc + 1];
        int grow = r0 + rr;
        int chunk = cc >> 5, c = cc & 31, gran = c >> 3, sub = (c & 7) * 2;
        size_t off = (size_t)chunk * 16384 + grow * 64 +
                     ((gran ^ ((grow >> 1) & 3)) << 4) + sub;
        *(uint32_t*)(Yh + off) = pack_hi(v0, v1);
        *(uint32_t*)(Yl + off) = pack_lo(v0, v1);
    }
}

// ---------------- q_mma: Q = I - Y V^T (bulk-staged, fp16 Q output) --------
#define QSTRIDE 32768u
__global__ void __launch_bounds__(256) q_mma() {
    extern __shared__ __align__(1024) char sm[];
    __shared__ __align__(8) uint64_t mbars[2];
    const uint32_t sb = smem_u32(sm);
    const uint32_t mb = smem_u32(mbars);
    int t = threadIdx.x, warp = t >> 5, lane = t & 31;
    int wm = warp >> 2, wn = warp & 3;
    int g = blockIdx.y;
    int a0 = (blockIdx.x >> 1) * 128, b0 = (blockIdx.x & 1) * 128;

    const unsigned char* Yh = g_Yq_h + (size_t)g * 131072;
    const unsigned char* Yl = g_Yq_l + (size_t)g * 131072;
    const unsigned char* Vh = g_Vq_h + (size_t)g * 131072;
    const unsigned char* Vl = g_Vq_l + (size_t)g * 131072;

    if (t == 0) { MBINIT(mb); MBINIT(mb + 8); }
    __syncthreads();

    auto stage = [&](int ch) {   // t == 0 only
        uint32_t mbar = mb + (uint32_t)(ch & 1) * 8;
        uint32_t d = sb + (uint32_t)(ch & 1) * QSTRIDE;
        EXPECT_TX(mbar, 32768u);
        BULK(d,         Yh + (size_t)ch * 16384 + a0 * 64, 8192u, mbar);
        BULK(d + 8192,  Yl + (size_t)ch * 16384 + a0 * 64, 8192u, mbar);
        BULK(d + 16384, Vh + (size_t)ch * 16384 + b0 * 64, 8192u, mbar);
        BULK(d + 24576, Vl + (size_t)ch * 16384 + b0 * 64, 8192u, mbar);
    };

    float acc[4][4][4] = {};
    if (t == 0) stage(0);
    for (int ch = 0; ch < 8; ++ch) {
        mbar_wait(mb + (uint32_t)(ch & 1) * 8, (uint32_t)((ch >> 1) & 1));
        __syncthreads();
        if (t == 0 && ch < 7) stage(ch + 1);
        uint32_t buf = sb + (uint32_t)(ch & 1) * QSTRIDE;
        #pragma unroll
        for (int ks = 0; ks < 32; ks += 16) {
            uint32_t ah[4][4], al[4][4];
            #pragma unroll
            for (int i = 0; i < 4; ++i) {
                uint32_t mrow = (uint32_t)(wm * 64 + i * 16 + (lane & 15));
                uint32_t gran = (uint32_t)((ks >> 3) + (lane >> 4));
                uint32_t addr = buf + mrow * 64u + ((gran ^ ((mrow >> 1) & 3)) << 4);
                LDSM4(ah[i], addr);
                LDSM4(al[i], addr + 8192);
            }
            #pragma unroll
            for (int p = 0; p < 2; ++p) {
                uint32_t bh[4], bl[4];
                uint32_t nrow = (uint32_t)(wn * 32 + p * 16 + (lane & 7) + ((lane >> 4) << 3));
                uint32_t gran = (uint32_t)((ks >> 3) + ((lane >> 3) & 1));
                uint32_t addr = buf + 16384 + nrow * 64u + ((gran ^ ((nrow >> 1) & 3)) << 4);
                LDSM4(bh, addr);
                LDSM4(bl, addr + 8192);
                #pragma unroll
                for (int i = 0; i < 4; ++i) {
                    MMA(acc[i][2 * p],     ah[i], bh[0], bh[1]);
                    MMA(acc[i][2 * p],     ah[i], bl[0], bl[1]);
                    MMA(acc[i][2 * p],     al[i], bh[0], bh[1]);
                    MMA(acc[i][2 * p + 1], ah[i], bh[2], bh[3]);
                    MMA(acc[i][2 * p + 1], ah[i], bl[2], bl[3]);
                    MMA(acc[i][2 * p + 1], al[i], bh[2], bh[3]);
                }
            }
        }
    }
    // epilogue: write single-fp16 swizzled global Q images
    unsigned char* QF = g_Qf_sw + (size_t)g * 8 * 16384;
    #pragma unroll
    for (int i = 0; i < 4; ++i) {
        int rr = a0 + wm * 64 + i * 16 + (lane >> 2);
        #pragma unroll
        for (int j = 0; j < 4; ++j) {
            int cc = b0 + wn * 32 + j * 8 + (lane & 3) * 2;
            float v0 = (rr == cc     ? 1.f : 0.f) - acc[i][j][0];
            float v1 = (rr == cc + 1 ? 1.f : 0.f) - acc[i][j][1];
            float v2 = (rr + 8 == cc     ? 1.f : 0.f) - acc[i][j][2];
            float v3 = (rr + 8 == cc + 1 ? 1.f : 0.f) - acc[i][j][3];
            int gran = cc >> 3, sub = (cc & 7) * 2;
            #pragma unroll
            for (int rh = 0; rh < 2; ++rh) {
                int k = rr + rh * 8;
                int chunk = k >> 5, krw = k & 31;
                size_t off = (size_t)chunk * 16384 + krw * 512 +
                             ((gran ^ (krw & 7)) << 4) + sub;
                *(uint32_t*)(QF + off) = pack_f16(rh ? v2 : v0, rh ? v3 : v1);
            }
        }
    }
}

// ---------------- out = x @ Q: fp16 2-term, BM=64, 2 CTAs/SM ---------------
#define BM 64
#define BN 256
#define BK 32
#define ABUF 10240u          // per A buffer: hi 5120 + lo 5120
#define BBASE 20480u
#define BBUF 16384u          // per B buffer: single fp16 Q image
#define SMEM_TOTAL (BBASE + 2u * BBUF)   // 53248

__global__ void __launch_bounds__(256, 2) main_mma(const float* __restrict__ X,
                                                   float* __restrict__ out) {
    extern __shared__ __align__(1024) char sm[];
    __shared__ __align__(8) uint64_t mbars[2];
    const uint32_t sbase = smem_u32(sm);
    const uint32_t mb_base = smem_u32(mbars);

    int t = threadIdx.x;
    int warp = t >> 5, lane = t & 31;
    int wm = warp >> 2, wn = warp & 3;      // warp tile 32m x 64n
    int g = blockIdx.y;
    int m0 = blockIdx.x * BM;

    const float* Xg = X + ((size_t)g * BSZ + m0) * CH;
    const unsigned char* QF = g_Qf_sw + (size_t)g * 8 * 16384;

    if (t == 0) { MBINIT(mb_base); MBINIT(mb_base + 8); }
    __syncthreads();

    int ar = t >> 2, ac = (t & 3) * 8;

    float acc[2][8][4] = {};
    float4 xa[2];

    auto loadA = [&](int ch) {
        xa[0] = *(const float4*)(Xg + (size_t)ar * CH + ch * BK + ac);
        xa[1] = *(const float4*)(Xg + (size_t)ar * CH + ch * BK + ac + 4);
    };
    auto issueB = [&](int ch) {   // t == 0 only
        int b = ch & 1;
        uint32_t mbar = mb_base + (uint32_t)b * 8;
        uint32_t dB = sbase + BBASE + (uint32_t)b * BBUF;
        EXPECT_TX(mbar, 16384u);
        BULK(dB, QF + (size_t)ch * 16384, 16384u, mbar);
    };
    auto storeA = [&](int ch) {
        char* p = sm + (ch & 1) * ABUF;
        float f[8] = {xa[0].x, xa[0].y, xa[0].z, xa[0].w,
                      xa[1].x, xa[1].y, xa[1].z, xa[1].w};
        uint32_t h[4], l[4];
        #pragma unroll
        for (int i = 0; i < 4; ++i) {
            h[i] = pack_f16(f[2 * i], f[2 * i + 1]);
            l[i] = pack_f16lo(f[2 * i], f[2 * i + 1]);
        }
        uint32_t ao = ar * 80u + ac * 2u;
        *(uint4*)(p + ao)        = make_uint4(h[0], h[1], h[2], h[3]);
        *(uint4*)(p + 5120 + ao) = make_uint4(l[0], l[1], l[2], l[3]);
    };

    loadA(0);
    if (t == 0) issueB(0);

    for (int ch = 0; ch < CH / BK; ++ch) {
        mbar_wait(mb_base + (uint32_t)(ch & 1) * 8, (uint32_t)((ch >> 1) & 1));
        storeA(ch);
        __syncthreads();
        if (t == 0 && ch + 1 < CH / BK) issueB(ch + 1);
        if (ch + 1 < CH / BK) loadA(ch + 1);

        uint32_t abuf = sbase + (uint32_t)(ch & 1) * ABUF;
        uint32_t bbuf = sbase + BBASE + (uint32_t)(ch & 1) * BBUF;
        #pragma unroll
        for (int ks = 0; ks < BK; ks += 16) {
            uint32_t ah[2][4], al[2][4];
            #pragma unroll
            for (int i = 0; i < 2; ++i) {
                uint32_t mrow = (uint32_t)(wm * 32 + i * 16 + (lane & 15));
                uint32_t kcol = (uint32_t)(ks + (lane >> 4) * 8);
                uint32_t addr = abuf + mrow * 80u + kcol * 2u;
                LDSM4(ah[i], addr);
                LDSM4(al[i], addr + 5120u);
            }
            #pragma unroll
            for (int p = 0; p < 4; ++p) {
                uint32_t bq[4];
                uint32_t krow = (uint32_t)(ks + (lane & 15));
                uint32_t gran = (uint32_t)(wn * 8 + p * 2 + (lane >> 4));
                uint32_t addr = bbuf + krow * 512u + ((gran ^ (krow & 7)) << 4);
                LDSM4T(bq, addr);
                #pragma unroll
                for (int i = 0; i < 2; ++i) {
                    MMAH(acc[i][2 * p],     ah[i], bq[0], bq[1]);
                    MMAH(acc[i][2 * p],     al[i], bq[0], bq[1]);
                    MMAH(acc[i][2 * p + 1], ah[i], bq[2], bq[3]);
                    MMAH(acc[i][2 * p + 1], al[i], bq[2], bq[3]);
                }
            }
        }
    }

    // epilogue
    #pragma unroll
    for (int i = 0; i < 2; ++i) {
        int row = m0 + wm * 32 + i * 16 + (lane >> 2);
        float* o0 = out + ((size_t)g * BSZ + row) * CH + wn * 64 + (lane & 3) * 2;
        #pragma unroll
        for (int j = 0; j < 8; ++j) {
            *(float2*)(o0 + j * 8)          = make_float2(acc[i][j][0], acc[i][j][1]);
            *(float2*)(o0 + 8 * CH + j * 8) = make_float2(acc[i][j][2], acc[i][j][3]);
        }
    }
}

// ---------------- entry ----------------------------------------------------
extern "C" void kernel_launch(void* const* d_in, const int* in_sizes, int n_in,
                              void* d_out, int out_size) {
    const float* x = (const float*)d_in[0];
    const float* w = (const float*)d_in[1];
    if (n_in >= 2 && in_sizes[0] < in_sizes[1]) {
        const float* tmp = x; x = w; w = tmp;
    }
    float* out = (float*)d_out;

    cudaFuncSetAttribute(main_mma, cudaFuncAttributeMaxDynamicSharedMemorySize,
                         SMEM_TOTAL);
    cudaFuncSetAttribute(g_mma, cudaFuncAttributeMaxDynamicSharedMemorySize, 65536);
    cudaFuncSetAttribute(q_mma, cudaFuncAttributeMaxDynamicSharedMemorySize, 65536);
    cudaFuncSetAttribute(y_kernel, cudaFuncAttributeMaxDynamicSharedMemorySize,
                         Y_SMEM_BYTES);
    cudaFuncSetAttribute(tinv_kernel, cudaFuncAttributeMaxDynamicSharedMemorySize,
                         TINV_SMEM);

    vsplit<<<GRP * CH * CH / 1024, 256>>>(w);

    dim3 ggrid(3, GRP);
    g_mma<<<ggrid, 256, 65536>>>();

    tinv_kernel<<<GRP, 256, TINV_SMEM>>>();

    dim3 ygrid(CH / 32, GRP);
    y_kernel<<<ygrid, 256, Y_SMEM_BYTES>>>(w);

    dim3 qgrid(4, GRP);
    q_mma<<<qgrid, 256, 65536>>>();

    dim3 mgrid(BSZ / BM, GRP);
    main_mma<<<mgrid, 256, SMEM_TOTAL>>>(x, out);
}

// round 17
// speedup vs baseline: 1.4780x; 1.1244x over previous
#include <cuda_runtime.h>
#include <cuda_bf16.h>
#include <cuda_fp16.h>
#include <cstdint>

#define GRP 16
#define BSZ 8192
#define CH  256

// ---------------- scratch (device globals; no allocation allowed) ----------
__device__ float g_Gu[GRP * 28 * 1024];         // strict-upper G blocks, packed
__device__ float g_Gd[GRP * 8 * 1024];          // diagonal G blocks
__device__ float g_Tinv[GRP * 8 * 1024];        // diag-block inverses of R
// V images for g_mma: [GRP][2 panels][8 kchunks][8192B] (32 krows x 256B, swz)
__device__ unsigned char g_Vg_h[GRP * 131072];
__device__ unsigned char g_Vg_l[GRP * 131072];
// V images for q_mma: [GRP][8 kchunks][256 rows][64B] (swz gran^((row>>1)&3))
__device__ unsigned char g_Vq_h[GRP * 131072];
__device__ unsigned char g_Vq_l[GRP * 131072];
// Y images (same layout as Vq)
__device__ unsigned char g_Yq_h[GRP * 131072];
__device__ unsigned char g_Yq_l[GRP * 131072];
// Q^T as single-fp16 pre-swizzled SMEM images: [GRP][8 chunks][16384B]
__device__ unsigned char g_Qf_sw[GRP * 8 * 16384];

__device__ __forceinline__ uint32_t smem_u32(const void* p) {
    uint32_t a;
    asm("{ .reg .u64 t; cvta.to.shared.u64 t, %1; cvt.u32.u64 %0, t; }"
        : "=r"(a) : "l"(p));
    return a;
}

#define LDSM4(r, addr)                                                      \
    asm volatile("ldmatrix.sync.aligned.m8n8.x4.shared.b16 {%0,%1,%2,%3}, [%4];" \
                 : "=r"((r)[0]), "=r"((r)[1]), "=r"((r)[2]), "=r"((r)[3])   \
                 : "r"(addr))
#define LDSM4T(r, addr)                                                     \
    asm volatile("ldmatrix.sync.aligned.m8n8.x4.trans.shared.b16 {%0,%1,%2,%3}, [%4];" \
                 : "=r"((r)[0]), "=r"((r)[1]), "=r"((r)[2]), "=r"((r)[3])   \
                 : "r"(addr))
#define MMA(c, a, b0, b1)                                                   \
    asm volatile("mma.sync.aligned.m16n8k16.row.col.f32.bf16.bf16.f32 "     \
                 "{%0,%1,%2,%3}, {%4,%5,%6,%7}, {%8,%9}, {%0,%1,%2,%3};"    \
                 : "+f"((c)[0]), "+f"((c)[1]), "+f"((c)[2]), "+f"((c)[3])   \
                 : "r"((a)[0]), "r"((a)[1]), "r"((a)[2]), "r"((a)[3]),      \
                   "r"(b0), "r"(b1))
#define MMAH(c, a, b0, b1)                                                  \
    asm volatile("mma.sync.aligned.m16n8k16.row.col.f32.f16.f16.f32 "       \
                 "{%0,%1,%2,%3}, {%4,%5,%6,%7}, {%8,%9}, {%0,%1,%2,%3};"    \
                 : "+f"((c)[0]), "+f"((c)[1]), "+f"((c)[2]), "+f"((c)[3])   \
                 : "r"((a)[0]), "r"((a)[1]), "r"((a)[2]), "r"((a)[3]),      \
                   "r"(b0), "r"(b1))
#define CP16(dst, src)                                                      \
    asm volatile("cp.async.cg.shared.global [%0], [%1], 16;"                \
                 :: "r"(dst), "l"(src) : "memory")
#define BULK(dst, src, bytes, mbar)                                         \
    asm volatile("cp.async.bulk.shared::cluster.global.mbarrier::complete_tx::bytes " \
                 "[%0], [%1], %2, [%3];"                                    \
                 :: "r"(dst), "l"(src), "r"(bytes), "r"(mbar) : "memory")
#define EXPECT_TX(mbar, bytes)                                              \
    asm volatile("mbarrier.arrive.expect_tx.shared.b64 _, [%0], %1;"        \
                 :: "r"(mbar), "r"(bytes) : "memory")
#define MBINIT(mbar)                                                        \
    asm volatile("mbarrier.init.shared.b64 [%0], 1;" :: "r"(mbar) : "memory")

__device__ __forceinline__ void mbar_wait(uint32_t mbar, uint32_t parity) {
    asm volatile(
        "{\n\t.reg .pred P;\n"
        "LW_%=:\n\t"
        "mbarrier.try_wait.parity.acquire.cta.shared::cta.b64 P, [%0], %1, 0x989680;\n\t"
        "@P bra LD_%=;\n\t"
        "bra LW_%=;\n"
        "LD_%=:\n\t}"
        :: "r"(mbar), "r"(parity) : "memory");
}

__device__ __forceinline__ uint32_t pack_hi(float a, float b) {
    __nv_bfloat16 x = __float2bfloat16(a), y = __float2bfloat16(b);
    return ((uint32_t)__bfloat16_as_ushort(y) << 16) | __bfloat16_as_ushort(x);
}
__device__ __forceinline__ uint32_t pack_lo(float a, float b) {
    __nv_bfloat16 x = __float2bfloat16(a), y = __float2bfloat16(b);
    __nv_bfloat16 lx = __float2bfloat16(a - __bfloat162float(x));
    __nv_bfloat16 ly = __float2bfloat16(b - __bfloat162float(y));
    return ((uint32_t)__bfloat16_as_ushort(ly) << 16) | __bfloat16_as_ushort(lx);
}
__device__ __forceinline__ uint32_t pack_f16(float a, float b) {
    __half x = __float2half_rn(a), y = __float2half_rn(b);
    return ((uint32_t)__half_as_ushort(y) << 16) | __half_as_ushort(x);
}

// ---------------- vsplit: W -> pre-swizzled hi/lo images (g & q layouts) ---
__global__ void vsplit(const float* __restrict__ W) {
    int idx4 = (blockIdx.x * 256 + threadIdx.x) * 4;
    int g = idx4 >> 16;
    int row = (idx4 >> 8) & 255, col = idx4 & 255;
    float4 v = *(const float4*)(W + idx4);
    uint2 h, l;
    h.x = pack_hi(v.x, v.y); h.y = pack_hi(v.z, v.w);
    l.x = pack_lo(v.x, v.y); l.y = pack_lo(v.z, v.w);
    // q layout
    {
        int chunk = col >> 5, c = col & 31, gran = c >> 3, sub = (c & 7) * 2;
        size_t off = (size_t)g * 131072 + chunk * 16384 + row * 64 +
                     ((gran ^ ((row >> 1) & 3)) << 4) + sub;
        *(uint2*)(g_Vq_h + off) = h;
        *(uint2*)(g_Vq_l + off) = l;
    }
    // g layout
    {
        int panel = col >> 7, cp = col & 127;
        int kch = row >> 5, kk = row & 31;
        int gr = cp >> 3, sg = (cp & 7) * 2;
        size_t off = (size_t)g * 131072 + panel * 65536 + kch * 8192 +
                     kk * 256 + ((gr ^ (kk & 7)) << 4) + sg;
        *(uint2*)(g_Vg_h + off) = h;
        *(uint2*)(g_Vg_l + off) = l;
    }
}

// ---------------- g_mma: G = V^T V (bulk-staged, packed-block output) ------
#define GSTRIDE 32768u
__global__ void __launch_bounds__(256) g_mma() {
    extern __shared__ __align__(1024) char sm[];
    __shared__ __align__(8) uint64_t mbars[2];
    const uint32_t sb = smem_u32(sm);
    const uint32_t mb = smem_u32(mbars);
    int t = threadIdx.x, warp = t >> 5, lane = t & 31;
    int wm = warp >> 2, wn = warp & 3;
    int g = blockIdx.y;
    int bx = blockIdx.x;                 // 0:(0,0) 1:(0,128) 2:(128,128)
    int a0 = (bx == 2) ? 128 : 0;
    int b0 = (bx == 0) ? 0 : 128;
    int pa = a0 >> 7, pb = b0 >> 7;

    const unsigned char* VAh = g_Vg_h + (size_t)g * 131072 + pa * 65536;
    const unsigned char* VAl = g_Vg_l + (size_t)g * 131072 + pa * 65536;
    const unsigned char* VBh = g_Vg_h + (size_t)g * 131072 + pb * 65536;
    const unsigned char* VBl = g_Vg_l + (size_t)g * 131072 + pb * 65536;

    if (t == 0) { MBINIT(mb); MBINIT(mb + 8); }
    __syncthreads();

    auto stage = [&](int ch) {   // t == 0 only
        uint32_t mbar = mb + (uint32_t)(ch & 1) * 8;
        uint32_t d = sb + (uint32_t)(ch & 1) * GSTRIDE;
        EXPECT_TX(mbar, 32768u);
        BULK(d,          VAh + ch * 8192, 8192u, mbar);
        BULK(d + 8192,   VAl + ch * 8192, 8192u, mbar);
        BULK(d + 16384,  VBh + ch * 8192, 8192u, mbar);
        BULK(d + 24576,  VBl + ch * 8192, 8192u, mbar);
    };

    float acc[4][4][4] = {};
    if (t == 0) stage(0);
    for (int ch = 0; ch < 8; ++ch) {
        mbar_wait(mb + (uint32_t)(ch & 1) * 8, (uint32_t)((ch >> 1) & 1));
        __syncthreads();
        if (t == 0 && ch < 7) stage(ch + 1);
        uint32_t buf = sb + (uint32_t)(ch & 1) * GSTRIDE;
        #pragma unroll
        for (int ks = 0; ks < 32; ks += 16) {
            uint32_t ah[4][4], al[4][4];
            #pragma unroll
            for (int i = 0; i < 4; ++i) {
                uint32_t mbcol = (uint32_t)(wm * 64 + i * 16);
                uint32_t krow = (uint32_t)(ks + (lane & 7) + ((lane >> 4) << 3));
                uint32_t gran = (mbcol >> 3) + ((lane >> 3) & 1);
                uint32_t addr = buf + krow * 256u + ((gran ^ (krow & 7)) << 4);
                LDSM4T(ah[i], addr);
                LDSM4T(al[i], addr + 8192);
            }
            #pragma unroll
            for (int p = 0; p < 2; ++p) {
                uint32_t bh[4], bl[4];
                uint32_t krow = (uint32_t)(ks + (lane & 15));
                uint32_t gran = (uint32_t)(wn * 4 + p * 2 + (lane >> 4));
                uint32_t addr = buf + 16384 + krow * 256u + ((gran ^ (krow & 7)) << 4);
                LDSM4T(bh, addr);
                LDSM4T(bl, addr + 8192);
                #pragma unroll
                for (int i = 0; i < 4; ++i) {
                    MMA(acc[i][2 * p],     ah[i], bh[0], bh[1]);
                    MMA(acc[i][2 * p],     ah[i], bl[0], bl[1]);
                    MMA(acc[i][2 * p],     al[i], bh[0], bh[1]);
                    MMA(acc[i][2 * p + 1], ah[i], bh[2], bh[3]);
                    MMA(acc[i][2 * p + 1], ah[i], bl[2], bl[3]);
                    MMA(acc[i][2 * p + 1], al[i], bh[2], bh[3]);
                }
            }
        }
    }
    // epilogue: packed strict-upper + diagonal block layout
    float* Gu = g_Gu + (size_t)g * 28 * 1024;
    float* Gd = g_Gd + (size_t)g * 8 * 1024;
    #pragma unroll
    for (int i = 0; i < 4; ++i) {
        int rowa = a0 + wm * 64 + i * 16 + (lane >> 2);
        #pragma unroll
        for (int j = 0; j < 4; ++j) {
            int colb = b0 + wn * 32 + j * 8 + (lane & 3) * 2;
            int kbb = colb >> 5;
            #pragma unroll
            for (int rh = 0; rh < 2; ++rh) {
                int row = rowa + rh * 8;
                int jcb = row >> 5;
                float2 v = make_float2(acc[i][j][2 * rh], acc[i][j][2 * rh + 1]);
                int boff = (row & 31) * 32 + (colb & 31);
                if (jcb < kbb)
                    *(float2*)&Gu[(kbb * (kbb - 1) / 2 + jcb) * 1024 + boff] = v;
                else if (jcb == kbb)
                    *(float2*)&Gd[kbb * 1024 + boff] = v;
            }
        }
    }
}

// ---------------- tinv: invert 32x32 diagonal blocks of R ------------------
#define TINV_SMEM ((8448 + 8448 + 256) * 4)
__global__ void __launch_bounds__(256) tinv_kernel() {
    extern __shared__ __align__(16) float S[];
    float* Gds = S;
    float* Ts  = S + 8448;
    float* bet = S + 16896;

    int g = blockIdx.x;
    int t = threadIdx.x;
    const float* Gsrc = g_Gd + (size_t)g * 8 * 1024;

    for (int e = t; e < 8192; e += 256) {
        int kb = e >> 10, i = (e >> 5) & 31, k = e & 31;
        Gds[kb * 1056 + i * 33 + k] = Gsrc[kb * 1024 + i * 32 + k];
    }
    {
        int kb = t >> 5, j = t & 31;
        bet[t] = 2.0f / Gsrc[kb * 1024 + j * 32 + j];
    }
    __syncthreads();

    int kb = t >> 5, j = t & 31;
    int c0 = kb * 32;
    float* Tb = Ts + kb * 1056;
    const float* Gb = Gds + kb * 1056;
    for (int i = j + 1; i < 32; ++i) Tb[i * 33 + j] = 0.f;
    Tb[j * 33 + j] = bet[c0 + j];
    for (int i = j - 1; i >= 0; --i) {
        float s = 0.f;
        for (int k = i + 1; k <= j; ++k)
            s += Gb[i * 33 + k] * Tb[k * 33 + j];
        Tb[i * 33 + j] = -bet[c0 + i] * s;
    }
    __syncthreads();
    float* Tg = g_Tinv + ((size_t)g * 8 + kb) * 1024;
    for (int i = 0; i < 32; ++i)
        Tg[i * 32 + j] = Tb[i * 33 + j];
}

// ---------------- Y = V R^{-1}: bulk-loaded panel, warp-parallel -----------
#define YGU   0
#define YTD   28672
#define YYS   36864
#define YPRE  45312
#define YSP   46464
#define Y_SMEM_FLOATS 55680
#define Y_SMEM_BYTES  (Y_SMEM_FLOATS * 4)
__global__ void __launch_bounds__(256) y_kernel(const float* __restrict__ W) {
    extern __shared__ __align__(128) float S[];
    __shared__ __align__(8) uint64_t ymb[1];
    const uint32_t sb = smem_u32(S);
    const uint32_t mb = smem_u32(ymb);
    int g  = blockIdx.y;
    int r0 = blockIdx.x * 32;
    int t  = threadIdx.x;

    const float* Vg = W + (size_t)g * CH * CH;

    if (t == 0) MBINIT(mb);
    __syncthreads();
    if (t == 0) {
        EXPECT_TX(mb, 147456u);
        const unsigned char* GuS = (const unsigned char*)(g_Gu + (size_t)g * 28 * 1024);
        const unsigned char* TdS = (const unsigned char*)(g_Tinv + (size_t)g * 8 * 1024);
        BULK(sb + YGU * 4,          GuS,          57344u, mb);
        BULK(sb + YGU * 4 + 57344,  GuS + 57344,  57344u, mb);
        BULK(sb + YTD * 4,          TdS,          32768u, mb);
    }
    {
        int rr = t >> 3, c = t & 7;
        for (int cc = c; cc < 64; cc += 8)
            CP16(sb + (uint32_t)(YYS + rr * 264 + cc * 4) * 4,
                 Vg + (size_t)(r0 + rr) * CH + cc * 4);
        asm volatile("cp.async.commit_group;" ::: "memory");
        asm volatile("cp.async.wait_group 0;" ::: "memory");
    }
    mbar_wait(mb, 0u);
    __syncthreads();

    int w = t >> 5, l = t & 31;
    int q = l & 7, r2 = l >> 3;
    int r = t >> 3, q8 = t & 7;

    for (int kb = 0; kb < 8; ++kb) {
        int c0 = kb * 32;
        float a[8][4] = {};
        int pbase = kb * (kb - 1) / 2;
        for (int jc = w; jc < kb; jc += 8) {
            const float* Gb = S + YGU + (pbase + jc) * 1024 + 4 * q;
            int j0 = jc * 32;
            #pragma unroll
            for (int jj = 0; jj < 32; ++jj) {
                float4 gg = *(const float4*)(Gb + jj * 32);
                #pragma unroll
                for (int ri = 0; ri < 8; ++ri) {
                    float yv = S[YYS + (r2 + 4 * ri) * 264 + j0 + jj];
                    a[ri][0] += yv * gg.x;
                    a[ri][1] += yv * gg.y;
                    a[ri][2] += yv * gg.z;
                    a[ri][3] += yv * gg.w;
                }
            }
        }
        #pragma unroll
        for (int ri = 0; ri < 8; ++ri) {
            float4 v = {a[ri][0], a[ri][1], a[ri][2], a[ri][3]};
            *(float4*)(S + YSP + w * 1152 + (r2 + 4 * ri) * 36 + 4 * q) = v;
        }
        __syncthreads();
        float4 pr = *(const float4*)(S + YYS + r * 264 + c0 + 4 * q8);
        #pragma unroll
        for (int w2 = 0; w2 < 8; ++w2) {
            float4 s = *(const float4*)(S + YSP + w2 * 1152 + r * 36 + 4 * q8);
            pr.x -= s.x; pr.y -= s.y; pr.z -= s.z; pr.w -= s.w;
        }
        *(float4*)(S + YPRE + r * 36 + 4 * q8) = pr;
        __syncwarp();
        const float* Tdb = S + YTD + kb * 1024 + 4 * q8;
        float o0 = 0.f, o1 = 0.f, o2 = 0.f, o3 = 0.f;
        #pragma unroll
        for (int i = 0; i < 32; ++i) {
            float pv = S[YPRE + r * 36 + i];
            float4 tv = *(const float4*)(Tdb + i * 32);
            o0 += pv * tv.x;
            o1 += pv * tv.y;
            o2 += pv * tv.z;
            o3 += pv * tv.w;
        }
        float4 ov = {o0, o1, o2, o3};
        *(float4*)(S + YYS + r * 264 + c0 + 4 * q8) = ov;
        __syncthreads();
    }

    // emit Y into q-friendly pre-swizzled images
    unsigned char* Yh = g_Yq_h + (size_t)g * 131072;
    unsigned char* Yl = g_Yq_l + (size_t)g * 131072;
    for (int e = t; e < 32 * (CH / 2); e += 256) {
        int rr = e >> 7, cc = (e & 127) * 2;
        float v0 = S[YYS + rr * 264 + cc], v1 = S[YYS + rr * 264 + cc + 1];
        int grow = r0 + rr;
        int chunk = cc >> 5, c = cc & 31, gran = c >> 3, sub = (c & 7) * 2;
        size_t off = (size_t)chunk * 16384 + grow * 64 +
                     ((gran ^ ((grow >> 1) & 3)) << 4) + sub;
        *(uint32_t*)(Yh + off) = pack_hi(v0, v1);
        *(uint32_t*)(Yl + off) = pack_lo(v0, v1);
    }
}

// ---------------- q_mma: Q = I - Y V^T (bulk-staged, fp16 Q output) --------
#define QSTRIDE 32768u
__global__ void __launch_bounds__(256) q_mma() {
    extern __shared__ __align__(1024) char sm[];
    __shared__ __align__(8) uint64_t mbars[2];
    const uint32_t sb = smem_u32(sm);
    const uint32_t mb = smem_u32(mbars);
    int t = threadIdx.x, warp = t >> 5, lane = t & 31;
    int wm = warp >> 2, wn = warp & 3;
    int g = blockIdx.y;
    int a0 = (blockIdx.x >> 1) * 128, b0 = (blockIdx.x & 1) * 128;

    const unsigned char* Yh = g_Yq_h + (size_t)g * 131072;
    const unsigned char* Yl = g_Yq_l + (size_t)g * 131072;
    const unsigned char* Vh = g_Vq_h + (size_t)g * 131072;
    const unsigned char* Vl = g_Vq_l + (size_t)g * 131072;

    if (t == 0) { MBINIT(mb); MBINIT(mb + 8); }
    __syncthreads();

    auto stage = [&](int ch) {   // t == 0 only
        uint32_t mbar = mb + (uint32_t)(ch & 1) * 8;
        uint32_t d = sb + (uint32_t)(ch & 1) * QSTRIDE;
        EXPECT_TX(mbar, 32768u);
        BULK(d,         Yh + (size_t)ch * 16384 + a0 * 64, 8192u, mbar);
        BULK(d + 8192,  Yl + (size_t)ch * 16384 + a0 * 64, 8192u, mbar);
        BULK(d + 16384, Vh + (size_t)ch * 16384 + b0 * 64, 8192u, mbar);
        BULK(d + 24576, Vl + (size_t)ch * 16384 + b0 * 64, 8192u, mbar);
    };

    float acc[4][4][4] = {};
    if (t == 0) stage(0);
    for (int ch = 0; ch < 8; ++ch) {
        mbar_wait(mb + (uint32_t)(ch & 1) * 8, (uint32_t)((ch >> 1) & 1));
        __syncthreads();
        if (t == 0 && ch < 7) stage(ch + 1);
        uint32_t buf = sb + (uint32_t)(ch & 1) * QSTRIDE;
        #pragma unroll
        for (int ks = 0; ks < 32; ks += 16) {
            uint32_t ah[4][4], al[4][4];
            #pragma unroll
            for (int i = 0; i < 4; ++i) {
                uint32_t mrow = (uint32_t)(wm * 64 + i * 16 + (lane & 15));
                uint32_t gran = (uint32_t)((ks >> 3) + (lane >> 4));
                uint32_t addr = buf + mrow * 64u + ((gran ^ ((mrow >> 1) & 3)) << 4);
                LDSM4(ah[i], addr);
                LDSM4(al[i], addr + 8192);
            }
            #pragma unroll
            for (int p = 0; p < 2; ++p) {
                uint32_t bh[4], bl[4];
                uint32_t nrow = (uint32_t)(wn * 32 + p * 16 + (lane & 7) + ((lane >> 4) << 3));
                uint32_t gran = (uint32_t)((ks >> 3) + ((lane >> 3) & 1));
                uint32_t addr = buf + 16384 + nrow * 64u + ((gran ^ ((nrow >> 1) & 3)) << 4);
                LDSM4(bh, addr);
                LDSM4(bl, addr + 8192);
                #pragma unroll
                for (int i = 0; i < 4; ++i) {
                    MMA(acc[i][2 * p],     ah[i], bh[0], bh[1]);
                    MMA(acc[i][2 * p],     ah[i], bl[0], bl[1]);
                    MMA(acc[i][2 * p],     al[i], bh[0], bh[1]);
                    MMA(acc[i][2 * p + 1], ah[i], bh[2], bh[3]);
                    MMA(acc[i][2 * p + 1], ah[i], bl[2], bl[3]);
                    MMA(acc[i][2 * p + 1], al[i], bh[2], bh[3]);
                }
            }
        }
    }
    // epilogue: write single-fp16 swizzled global Q images
    unsigned char* QF = g_Qf_sw + (size_t)g * 8 * 16384;
    #pragma unroll
    for (int i = 0; i < 4; ++i) {
        int rr = a0 + wm * 64 + i * 16 + (lane >> 2);
        #pragma unroll
        for (int j = 0; j < 4; ++j) {
            int cc = b0 + wn * 32 + j * 8 + (lane & 3) * 2;
            float v0 = (rr == cc     ? 1.f : 0.f) - acc[i][j][0];
            float v1 = (rr == cc + 1 ? 1.f : 0.f) - acc[i][j][1];
            float v2 = (rr + 8 == cc     ? 1.f : 0.f) - acc[i][j][2];
            float v3 = (rr + 8 == cc + 1 ? 1.f : 0.f) - acc[i][j][3];
            int gran = cc >> 3, sub = (cc & 7) * 2;
            #pragma unroll
            for (int rh = 0; rh < 2; ++rh) {
                int k = rr + rh * 8;
                int chunk = k >> 5, krw = k & 31;
                size_t off = (size_t)chunk * 16384 + krw * 512 +
                             ((gran ^ (krw & 7)) << 4) + sub;
                *(uint32_t*)(QF + off) = pack_f16(rh ? v2 : v0, rh ? v3 : v1);
            }
        }
    }
}

// ---------------- out = x @ Q: pure-fp16 1-term, BM=64, 2 CTAs/SM ----------
#define BM 64
#define BN 256
#define BK 32
#define ABUF 5120u           // per A buffer: single fp16, 64 rows x 80B
#define BBASE 10240u
#define BBUF 16384u          // per B buffer: single fp16 Q image
#define SMEM_TOTAL (BBASE + 2u * BBUF)   // 43008

__global__ void __launch_bounds__(256, 2) main_mma(const float* __restrict__ X,
                                                   float* __restrict__ out) {
    extern __shared__ __align__(1024) char sm[];
    __shared__ __align__(8) uint64_t mbars[2];
    const uint32_t sbase = smem_u32(sm);
    const uint32_t mb_base = smem_u32(mbars);

    int t = threadIdx.x;
    int warp = t >> 5, lane = t & 31;
    int wm = warp >> 2, wn = warp & 3;      // warp tile 32m x 64n
    int g = blockIdx.y;
    int m0 = blockIdx.x * BM;

    const float* Xg = X + ((size_t)g * BSZ + m0) * CH;
    const unsigned char* QF = g_Qf_sw + (size_t)g * 8 * 16384;

    if (t == 0) { MBINIT(mb_base); MBINIT(mb_base + 8); }
    __syncthreads();

    int ar = t >> 2, ac = (t & 3) * 8;

    float acc[2][8][4] = {};
    float4 xa[2];

    auto loadA = [&](int ch) {
        xa[0] = *(const float4*)(Xg + (size_t)ar * CH + ch * BK + ac);
        xa[1] = *(const float4*)(Xg + (size_t)ar * CH + ch * BK + ac + 4);
    };
    auto issueB = [&](int ch) {   // t == 0 only
        int b = ch & 1;
        uint32_t mbar = mb_base + (uint32_t)b * 8;
        uint32_t dB = sbase + BBASE + (uint32_t)b * BBUF;
        EXPECT_TX(mbar, 16384u);
        BULK(dB, QF + (size_t)ch * 16384, 16384u, mbar);
    };
    auto storeA = [&](int ch) {
        char* p = sm + (ch & 1) * ABUF;
        float f[8] = {xa[0].x, xa[0].y, xa[0].z, xa[0].w,
                      xa[1].x, xa[1].y, xa[1].z, xa[1].w};
        uint32_t h[4];
        #pragma unroll
        for (int i = 0; i < 4; ++i)
            h[i] = pack_f16(f[2 * i], f[2 * i + 1]);
        uint32_t ao = ar * 80u + ac * 2u;
        *(uint4*)(p + ao) = make_uint4(h[0], h[1], h[2], h[3]);
    };

    loadA(0);
    if (t == 0) issueB(0);

    for (int ch = 0; ch < CH / BK; ++ch) {
        mbar_wait(mb_base + (uint32_t)(ch & 1) * 8, (uint32_t)((ch >> 1) & 1));
        storeA(ch);
        __syncthreads();
        if (t == 0 && ch + 1 < CH / BK) issueB(ch + 1);
        if (ch + 1 < CH / BK) loadA(ch + 1);

        uint32_t abuf = sbase + (uint32_t)(ch & 1) * ABUF;
        uint32_t bbuf = sbase + BBASE + (uint32_t)(ch & 1) * BBUF;
        #pragma unroll
        for (int ks = 0; ks < BK; ks += 16) {
            uint32_t ah[2][4];
            #pragma unroll
            for (int i = 0; i < 2; ++i) {
                uint32_t mrow = (uint32_t)(wm * 32 + i * 16 + (lane & 15));
                uint32_t kcol = (uint32_t)(ks + (lane >> 4) * 8);
                uint32_t addr = abuf + mrow * 80u + kcol * 2u;
                LDSM4(ah[i], addr);
            }
            #pragma unroll
            for (int p = 0; p < 4; ++p) {
                uint32_t bq[4];
                uint32_t krow = (uint32_t)(ks + (lane & 15));
                uint32_t gran = (uint32_t)(wn * 8 + p * 2 + (lane >> 4));
                uint32_t addr = bbuf + krow * 512u + ((gran ^ (krow & 7)) << 4);
                LDSM4T(bq, addr);
                #pragma unroll
                for (int i = 0; i < 2; ++i) {
                    MMAH(acc[i][2 * p],     ah[i], bq[0], bq[1]);
                    MMAH(acc[i][2 * p + 1], ah[i], bq[2], bq[3]);
                }
            }
        }
    }

    // epilogue
    #pragma unroll
    for (int i = 0; i < 2; ++i) {
        int row = m0 + wm * 32 + i * 16 + (lane >> 2);
        float* o0 = out + ((size_t)g * BSZ + row) * CH + wn * 64 + (lane & 3) * 2;
        #pragma unroll
        for (int j = 0; j < 8; ++j) {
            *(float2*)(o0 + j * 8)          = make_float2(acc[i][j][0], acc[i][j][1]);
            *(float2*)(o0 + 8 * CH + j * 8) = make_float2(acc[i][j][2], acc[i][j][3]);
        }
    }
}

// ---------------- entry ----------------------------------------------------
extern "C" void kernel_launch(void* const* d_in, const int* in_sizes, int n_in,
                              void* d_out, int out_size) {
    const float* x = (const float*)d_in[0];
    const float* w = (const float*)d_in[1];
    if (n_in >= 2 && in_sizes[0] < in_sizes[1]) {
        const float* tmp = x; x = w; w = tmp;
    }
    float* out = (float*)d_out;

    cudaFuncSetAttribute(main_mma, cudaFuncAttributeMaxDynamicSharedMemorySize,
                         SMEM_TOTAL);
    cudaFuncSetAttribute(g_mma, cudaFuncAttributeMaxDynamicSharedMemorySize, 65536);
    cudaFuncSetAttribute(q_mma, cudaFuncAttributeMaxDynamicSharedMemorySize, 65536);
    cudaFuncSetAttribute(y_kernel, cudaFuncAttributeMaxDynamicSharedMemorySize,
                         Y_SMEM_BYTES);
    cudaFuncSetAttribute(tinv_kernel, cudaFuncAttributeMaxDynamicSharedMemorySize,
                         TINV_SMEM);

    vsplit<<<GRP * CH * CH / 1024, 256>>>(w);

    dim3 ggrid(3, GRP);
    g_mma<<<ggrid, 256, 65536>>>();

    tinv_kernel<<<GRP, 256, TINV_SMEM>>>();

    dim3 ygrid(CH / 32, GRP);
    y_kernel<<<ygrid, 256, Y_SMEM_BYTES>>>(w);

    dim3 qgrid(4, GRP);
    q_mma<<<qgrid, 256, 65536>>>();

    dim3 mgrid(BSZ / BM, GRP);
    main_mma<<<mgrid, 256, SMEM_TOTAL>>>(x, out);
}